// round 1
// baseline (speedup 1.0000x reference)
#include <cuda_runtime.h>
#include <cuda_bf16.h>
#include <math.h>

// ---------------- problem constants ----------------
#define BATCH 2
#define TT    1024
#define CC    768
#define HH    12
#define DD    64
#define LL    12
#define MROWS (BATCH*TT)      // 2048
#define C3    (3*CC)          // 2304
#define C4    (4*CC)          // 3072
#define VP    50304

// ---------------- scratch (device globals; no allocation allowed) ----------
__device__ float g_x  [MROWS*CC];
__device__ float g_ln [MROWS*CC];
__device__ float g_qkv[MROWS*C3];
__device__ float g_att[MROWS*CC];
__device__ float g_act[MROWS*C4];

// ---------------- embedding ----------------
__global__ void embed_kernel(const int* __restrict__ idx,
                             const float* __restrict__ wte,
                             const float* __restrict__ wpe,
                             float* __restrict__ x)
{
    int m = blockIdx.x;            // 0..2047
    int t = m & (TT-1);
    int tok = idx[m];
    const float* we = wte + (size_t)tok * CC;
    const float* wp = wpe + (size_t)t * CC;
    float* xr = x + (size_t)m * CC;
    for (int c = threadIdx.x; c < CC; c += blockDim.x)
        xr[c] = we[c] + wp[c];
}

// ---------------- layernorm (one block per row, 256 threads, 3 elems/thread)
__global__ void ln_kernel(const float* __restrict__ x,
                          const float* __restrict__ w,
                          const float* __restrict__ b,
                          float* __restrict__ y)
{
    __shared__ float red[256];
    int row = blockIdx.x;
    int tid = threadIdx.x;
    const float* xr = x + (size_t)row * CC;

    float v0 = xr[tid], v1 = xr[tid+256], v2 = xr[tid+512];
    float local = v0 + v1 + v2;
    red[tid] = local; __syncthreads();
    for (int s = 128; s > 0; s >>= 1) {
        if (tid < s) red[tid] += red[tid+s];
        __syncthreads();
    }
    float mu = red[0] * (1.0f/CC);
    __syncthreads();

    float d0 = v0-mu, d1 = v1-mu, d2 = v2-mu;
    red[tid] = d0*d0 + d1*d1 + d2*d2; __syncthreads();
    for (int s = 128; s > 0; s >>= 1) {
        if (tid < s) red[tid] += red[tid+s];
        __syncthreads();
    }
    float rstd = rsqrtf(red[0] * (1.0f/CC) + 1e-5f);

    float* yr = y + (size_t)row * CC;
    yr[tid]     = d0*rstd*w[tid]     + b[tid];
    yr[tid+256] = d1*rstd*w[tid+256] + b[tid+256];
    yr[tid+512] = d2*rstd*w[tid+512] + b[tid+512];
}

// ---------------- generic TN SGEMM: Y[m,n] = sum_k X[m,k]*W[n,k] (+bias)(+res)(gelu)
// Tile 128x128, BK=16, 256 threads, 8x8 per-thread micro-tile.
// Requires M%128==0, N%128==0, K%16==0 (all shapes here satisfy this).
#define BM 128
#define BN 128
#define BK 16
#define LDT 132   // padded smem row stride (floats), multiple of 4 for float4 align

__device__ __forceinline__ float gelu_tanh(float x) {
    float x3 = x*x*x;
    return 0.5f * x * (1.0f + tanhf(0.7978845608028654f * (x + 0.044715f * x3)));
}

template<bool GELU, bool RES>
__global__ void __launch_bounds__(256)
gemm_tn(const float* __restrict__ X, const float* __restrict__ W,
        const float* __restrict__ bias, const float* __restrict__ res,
        float* __restrict__ Y, int M, int N, int K)
{
    __shared__ float As[BK][LDT];
    __shared__ float Bs[BK][LDT];

    const int tid = threadIdx.x;
    const int bm = blockIdx.y * BM;
    const int bn = blockIdx.x * BN;
    const int ty = tid >> 4;   // 0..15
    const int tx = tid & 15;   // 0..15

    float acc[8][8];
    #pragma unroll
    for (int i = 0; i < 8; i++)
        #pragma unroll
        for (int j = 0; j < 8; j++) acc[i][j] = 0.0f;

    for (int k0 = 0; k0 < K; k0 += BK) {
        // load tiles: 512 float4 each, 2 per thread
        #pragma unroll
        for (int i = 0; i < 2; i++) {
            int v   = tid + i*256;
            int row = v >> 2;
            int kc  = (v & 3) * 4;
            float4 a = *(const float4*)&X[(size_t)(bm+row)*K + k0 + kc];
            As[kc+0][row] = a.x; As[kc+1][row] = a.y;
            As[kc+2][row] = a.z; As[kc+3][row] = a.w;
            float4 bb = *(const float4*)&W[(size_t)(bn+row)*K + k0 + kc];
            Bs[kc+0][row] = bb.x; Bs[kc+1][row] = bb.y;
            Bs[kc+2][row] = bb.z; Bs[kc+3][row] = bb.w;
        }
        __syncthreads();

        #pragma unroll
        for (int k = 0; k < BK; k++) {
            float a[8], b[8];
            *(float4*)&a[0] = *(float4*)&As[k][ty*4];
            *(float4*)&a[4] = *(float4*)&As[k][ty*4 + 64];
            *(float4*)&b[0] = *(float4*)&Bs[k][tx*4];
            *(float4*)&b[4] = *(float4*)&Bs[k][tx*4 + 64];
            #pragma unroll
            for (int i = 0; i < 8; i++)
                #pragma unroll
                for (int j = 0; j < 8; j++)
                    acc[i][j] = fmaf(a[i], b[j], acc[i][j]);
        }
        __syncthreads();
    }

    // epilogue
    float bv[8];
    #pragma unroll
    for (int jj = 0; jj < 2; jj++)
        #pragma unroll
        for (int j = 0; j < 4; j++)
            bv[jj*4+j] = bias ? bias[bn + tx*4 + jj*64 + j] : 0.0f;

    #pragma unroll
    for (int ii = 0; ii < 2; ii++) {
        #pragma unroll
        for (int i = 0; i < 4; i++) {
            int m = bm + ty*4 + ii*64 + i;
            float* yr = Y + (size_t)m * N + bn;
            const float* rr = RES ? (res + (size_t)m * N + bn) : nullptr;
            #pragma unroll
            for (int jj = 0; jj < 2; jj++) {
                int no = tx*4 + jj*64;
                float4 r;
                float v0 = acc[ii*4+i][jj*4+0] + bv[jj*4+0];
                float v1 = acc[ii*4+i][jj*4+1] + bv[jj*4+1];
                float v2 = acc[ii*4+i][jj*4+2] + bv[jj*4+2];
                float v3 = acc[ii*4+i][jj*4+3] + bv[jj*4+3];
                if (GELU) { v0=gelu_tanh(v0); v1=gelu_tanh(v1); v2=gelu_tanh(v2); v3=gelu_tanh(v3); }
                if (RES)  {
                    float4 rv = *(const float4*)&rr[no];
                    v0 += rv.x; v1 += rv.y; v2 += rv.z; v3 += rv.w;
                }
                r.x=v0; r.y=v1; r.z=v2; r.w=v3;
                *(float4*)&yr[no] = r;
            }
        }
    }
}

// ---------------- attention: one block per (b,h,q), 128 threads ----------------
__global__ void __launch_bounds__(128)
attn_kernel(const float* __restrict__ qkv, float* __restrict__ y)
{
    __shared__ float sc[TT];
    __shared__ float qs[DD];
    __shared__ float red[128];

    const int t = blockIdx.x;
    const int h = blockIdx.y;
    const int b = blockIdx.z;
    const int tid = threadIdx.x;
    const int nk = t + 1;

    const float* qrow = qkv + ((size_t)(b*TT + t) * C3) + h*DD;
    if (tid < DD) qs[tid] = qrow[tid] * 0.125f;   // 1/sqrt(64)
    __syncthreads();

    // scores
    float lmax = -1e30f;
    for (int k = tid; k < nk; k += 128) {
        const float* krow = qkv + ((size_t)(b*TT + k) * C3) + CC + h*DD;
        float s = 0.0f;
        #pragma unroll
        for (int d4 = 0; d4 < DD; d4 += 4) {
            float4 kv = *(const float4*)&krow[d4];
            s += qs[d4+0]*kv.x + qs[d4+1]*kv.y + qs[d4+2]*kv.z + qs[d4+3]*kv.w;
        }
        sc[k] = s;
        lmax = fmaxf(lmax, s);
    }
    red[tid] = lmax; __syncthreads();
    for (int s = 64; s > 0; s >>= 1) {
        if (tid < s) red[tid] = fmaxf(red[tid], red[tid+s]);
        __syncthreads();
    }
    float mx = red[0];
    __syncthreads();

    float lsum = 0.0f;
    for (int k = tid; k < nk; k += 128) {
        float e = __expf(sc[k] - mx);
        sc[k] = e;
        lsum += e;
    }
    red[tid] = lsum; __syncthreads();
    for (int s = 64; s > 0; s >>= 1) {
        if (tid < s) red[tid] += red[tid+s];
        __syncthreads();
    }
    float inv = 1.0f / red[0];
    __syncthreads();

    // output: threads 0..63 each own one d; V row stride = 3C
    if (tid < DD) {
        const float* vp = qkv + ((size_t)(b*TT) * C3) + 2*CC + h*DD + tid;
        float o = 0.0f;
        int k = 0;
        for (; k + 4 <= nk; k += 4) {
            o += sc[k+0] * vp[(size_t)(k+0)*C3];
            o += sc[k+1] * vp[(size_t)(k+1)*C3];
            o += sc[k+2] * vp[(size_t)(k+2)*C3];
            o += sc[k+3] * vp[(size_t)(k+3)*C3];
        }
        for (; k < nk; k++) o += sc[k] * vp[(size_t)k*C3];
        y[(size_t)(b*TT + t) * CC + h*DD + tid] = o * inv;
    }
}

// ---------------- launch ----------------
extern "C" void kernel_launch(void* const* d_in, const int* in_sizes, int n_in,
                              void* d_out, int out_size)
{
    (void)in_sizes; (void)n_in; (void)out_size;
    const int*   idx     = (const int*)  d_in[0];
    const float* wte     = (const float*)d_in[1];
    const float* wpe     = (const float*)d_in[2];
    const float* ln1w    = (const float*)d_in[3];
    const float* ln1b    = (const float*)d_in[4];
    const float* qkvw    = (const float*)d_in[5];
    const float* qkvb    = (const float*)d_in[6];
    const float* projw   = (const float*)d_in[7];
    const float* projb   = (const float*)d_in[8];
    const float* ln2w    = (const float*)d_in[9];
    const float* ln2b    = (const float*)d_in[10];
    const float* fcw     = (const float*)d_in[11];
    const float* fcb     = (const float*)d_in[12];
    const float* fcprojw = (const float*)d_in[13];
    const float* fcprojb = (const float*)d_in[14];
    const float* lnfw    = (const float*)d_in[15];
    const float* lnfb    = (const float*)d_in[16];
    float* out = (float*)d_out;

    float *x, *ln, *qkv, *att, *act;
    cudaGetSymbolAddress((void**)&x,   g_x);
    cudaGetSymbolAddress((void**)&ln,  g_ln);
    cudaGetSymbolAddress((void**)&qkv, g_qkv);
    cudaGetSymbolAddress((void**)&att, g_att);
    cudaGetSymbolAddress((void**)&act, g_act);

    dim3 thr256(256);

    embed_kernel<<<MROWS, 256>>>(idx, wte, wpe, x);

    for (int l = 0; l < LL; l++) {
        ln_kernel<<<MROWS, 256>>>(x, ln1w + l*CC, ln1b + l*CC, ln);

        gemm_tn<false,false><<<dim3(C3/BN, MROWS/BM), thr256>>>(
            ln, qkvw + (size_t)l*C3*CC, qkvb + (size_t)l*C3, nullptr,
            qkv, MROWS, C3, CC);

        attn_kernel<<<dim3(TT, HH, BATCH), 128>>>(qkv, att);

        gemm_tn<false,true><<<dim3(CC/BN, MROWS/BM), thr256>>>(
            att, projw + (size_t)l*CC*CC, projb + (size_t)l*CC, x,
            x, MROWS, CC, CC);

        ln_kernel<<<MROWS, 256>>>(x, ln2w + l*CC, ln2b + l*CC, ln);

        gemm_tn<true,false><<<dim3(C4/BN, MROWS/BM), thr256>>>(
            ln, fcw + (size_t)l*C4*CC, fcb + (size_t)l*C4, nullptr,
            act, MROWS, C4, CC);

        gemm_tn<false,true><<<dim3(CC/BN, MROWS/BM), thr256>>>(
            act, fcprojw + (size_t)l*CC*C4, fcprojb + (size_t)l*CC, x,
            x, MROWS, CC, C4);
    }

    ln_kernel<<<MROWS, 256>>>(x, lnfw, lnfb, ln);

    gemm_tn<false,false><<<dim3(VP/BN, MROWS/BM), thr256>>>(
        ln, wte, nullptr, nullptr, out, MROWS, VP, CC);
}

// round 2
// speedup vs baseline: 1.5398x; 1.5398x over previous
#include <cuda_runtime.h>
#include <cuda_bf16.h>
#include <math.h>

// ---------------- problem constants ----------------
#define BATCH 2
#define TT    1024
#define CC    768
#define HH    12
#define DD    64
#define LL    12
#define MROWS (BATCH*TT)      // 2048
#define C3    (3*CC)          // 2304
#define C4    (4*CC)          // 3072
#define VP    50304

// ---------------- scratch (device globals; no allocation allowed) ----------
__device__ float g_x  [MROWS*CC];
__device__ float g_ln [MROWS*CC];
__device__ float g_qkv[MROWS*C3];
__device__ float g_att[MROWS*CC];
__device__ float g_act[MROWS*C4];

// ---------------- embedding ----------------
__global__ void embed_kernel(const int* __restrict__ idx,
                             const float* __restrict__ wte,
                             const float* __restrict__ wpe,
                             float* __restrict__ x)
{
    int m = blockIdx.x;            // 0..2047
    int t = m & (TT-1);
    int tok = idx[m];
    const float* we = wte + (size_t)tok * CC;
    const float* wp = wpe + (size_t)t * CC;
    float* xr = x + (size_t)m * CC;
    for (int c = threadIdx.x; c < CC; c += blockDim.x)
        xr[c] = we[c] + wp[c];
}

// ---------------- layernorm (one block per row, 256 threads, 3 elems/thread)
__global__ void ln_kernel(const float* __restrict__ x,
                          const float* __restrict__ w,
                          const float* __restrict__ b,
                          float* __restrict__ y)
{
    __shared__ float red[256];
    int row = blockIdx.x;
    int tid = threadIdx.x;
    const float* xr = x + (size_t)row * CC;

    float v0 = xr[tid], v1 = xr[tid+256], v2 = xr[tid+512];
    float local = v0 + v1 + v2;
    red[tid] = local; __syncthreads();
    for (int s = 128; s > 0; s >>= 1) {
        if (tid < s) red[tid] += red[tid+s];
        __syncthreads();
    }
    float mu = red[0] * (1.0f/CC);
    __syncthreads();

    float d0 = v0-mu, d1 = v1-mu, d2 = v2-mu;
    red[tid] = d0*d0 + d1*d1 + d2*d2; __syncthreads();
    for (int s = 128; s > 0; s >>= 1) {
        if (tid < s) red[tid] += red[tid+s];
        __syncthreads();
    }
    float rstd = rsqrtf(red[0] * (1.0f/CC) + 1e-5f);

    float* yr = y + (size_t)row * CC;
    yr[tid]     = d0*rstd*w[tid]     + b[tid];
    yr[tid+256] = d1*rstd*w[tid+256] + b[tid+256];
    yr[tid+512] = d2*rstd*w[tid+512] + b[tid+512];
}

// ---------------- generic TN SGEMM: Y[m,n] = sum_k X[m,k]*W[n,k] (+bias)(+res)(gelu)
#define BM 128
#define BN 128
#define BK 16
#define LDT 132

__device__ __forceinline__ float gelu_tanh(float x) {
    float x3 = x*x*x;
    return 0.5f * x * (1.0f + tanhf(0.7978845608028654f * (x + 0.044715f * x3)));
}

template<bool GELU, bool RES>
__global__ void __launch_bounds__(256)
gemm_tn(const float* __restrict__ X, const float* __restrict__ W,
        const float* __restrict__ bias, const float* __restrict__ res,
        float* __restrict__ Y, int M, int N, int K)
{
    __shared__ float As[BK][LDT];
    __shared__ float Bs[BK][LDT];

    const int tid = threadIdx.x;
    const int bm = blockIdx.y * BM;
    const int bn = blockIdx.x * BN;
    const int ty = tid >> 4;   // 0..15
    const int tx = tid & 15;   // 0..15

    float acc[8][8];
    #pragma unroll
    for (int i = 0; i < 8; i++)
        #pragma unroll
        for (int j = 0; j < 8; j++) acc[i][j] = 0.0f;

    for (int k0 = 0; k0 < K; k0 += BK) {
        #pragma unroll
        for (int i = 0; i < 2; i++) {
            int v   = tid + i*256;
            int row = v >> 2;
            int kc  = (v & 3) * 4;
            float4 a = *(const float4*)&X[(size_t)(bm+row)*K + k0 + kc];
            As[kc+0][row] = a.x; As[kc+1][row] = a.y;
            As[kc+2][row] = a.z; As[kc+3][row] = a.w;
            float4 bb = *(const float4*)&W[(size_t)(bn+row)*K + k0 + kc];
            Bs[kc+0][row] = bb.x; Bs[kc+1][row] = bb.y;
            Bs[kc+2][row] = bb.z; Bs[kc+3][row] = bb.w;
        }
        __syncthreads();

        #pragma unroll
        for (int k = 0; k < BK; k++) {
            float a[8], b[8];
            *(float4*)&a[0] = *(float4*)&As[k][ty*4];
            *(float4*)&a[4] = *(float4*)&As[k][ty*4 + 64];
            *(float4*)&b[0] = *(float4*)&Bs[k][tx*4];
            *(float4*)&b[4] = *(float4*)&Bs[k][tx*4 + 64];
            #pragma unroll
            for (int i = 0; i < 8; i++)
                #pragma unroll
                for (int j = 0; j < 8; j++)
                    acc[i][j] = fmaf(a[i], b[j], acc[i][j]);
        }
        __syncthreads();
    }

    float bv[8];
    #pragma unroll
    for (int jj = 0; jj < 2; jj++)
        #pragma unroll
        for (int j = 0; j < 4; j++)
            bv[jj*4+j] = bias ? bias[bn + tx*4 + jj*64 + j] : 0.0f;

    #pragma unroll
    for (int ii = 0; ii < 2; ii++) {
        #pragma unroll
        for (int i = 0; i < 4; i++) {
            int m = bm + ty*4 + ii*64 + i;
            float* yr = Y + (size_t)m * N + bn;
            const float* rr = RES ? (res + (size_t)m * N + bn) : nullptr;
            #pragma unroll
            for (int jj = 0; jj < 2; jj++) {
                int no = tx*4 + jj*64;
                float4 r;
                float v0 = acc[ii*4+i][jj*4+0] + bv[jj*4+0];
                float v1 = acc[ii*4+i][jj*4+1] + bv[jj*4+1];
                float v2 = acc[ii*4+i][jj*4+2] + bv[jj*4+2];
                float v3 = acc[ii*4+i][jj*4+3] + bv[jj*4+3];
                if (GELU) { v0=gelu_tanh(v0); v1=gelu_tanh(v1); v2=gelu_tanh(v2); v3=gelu_tanh(v3); }
                if (RES)  {
                    float4 rv = *(const float4*)&rr[no];
                    v0 += rv.x; v1 += rv.y; v2 += rv.z; v3 += rv.w;
                }
                r.x=v0; r.y=v1; r.z=v2; r.w=v3;
                *(float4*)&yr[no] = r;
            }
        }
    }
}

// ---------------- flash attention: 64 queries/block, 32-key tiles ----------------
// 256 threads as 16x16: ty = tid/16 owns 4 queries (ty*4..+3),
// tx = tid%16 owns 2 keys (score stage) / 4 d-components (output stage).
#define AQ 64
#define AK 32

__global__ void __launch_bounds__(256)
attn_kernel(const float* __restrict__ qkv, float* __restrict__ y)
{
    __shared__ float Qs[64][68];   // [d][q]  (transposed, scaled)
    __shared__ float Ks[64][34];   // [d][k]  (transposed)
    __shared__ float Vs[AK][68];   // [k][d]
    __shared__ float Ps[64][36];   // [q][k]  probabilities

    const int qt  = blockIdx.x;    // 0..15
    const int h   = blockIdx.y;
    const int b   = blockIdx.z;
    const int tid = threadIdx.x;
    const int tx  = tid & 15;
    const int ty  = tid >> 4;
    const int q0  = qt * AQ;

    const float* qbase = qkv + (size_t)(b*TT)*C3 + h*DD;
    const float* kbase = qbase + CC;
    const float* vbase = qbase + 2*CC;

    // load Q tile transposed + pre-scaled: 64q x 16 float4, 4 per thread
    #pragma unroll
    for (int i = 0; i < 4; i++) {
        int v  = tid + i*256;
        int q  = v >> 4;
        int d4 = (v & 15) * 4;
        float4 t = *(const float4*)&qbase[(size_t)(q0+q)*C3 + d4];
        Qs[d4+0][q] = t.x*0.125f; Qs[d4+1][q] = t.y*0.125f;
        Qs[d4+2][q] = t.z*0.125f; Qs[d4+3][q] = t.w*0.125f;
    }

    float o[4][4];
    float m[4], l[4];
    #pragma unroll
    for (int i = 0; i < 4; i++) {
        m[i] = -1e30f; l[i] = 0.0f;
        o[i][0]=0.f; o[i][1]=0.f; o[i][2]=0.f; o[i][3]=0.f;
    }

    const int ntiles = (q0 + AQ) / AK;   // 2*(qt+1)
    for (int kt = 0; kt < ntiles; kt++) {
        __syncthreads();   // previous tile's Ps/Vs reads done; Qs visible on kt==0

        // load K (transposed) and V tiles: 32k x 16 float4, 2 per thread
        #pragma unroll
        for (int i = 0; i < 2; i++) {
            int v  = tid + i*256;
            int k  = v >> 4;
            int d4 = (v & 15) * 4;
            size_t roff = (size_t)(kt*AK + k)*C3 + d4;
            float4 t = *(const float4*)&kbase[roff];
            Ks[d4+0][k]=t.x; Ks[d4+1][k]=t.y; Ks[d4+2][k]=t.z; Ks[d4+3][k]=t.w;
            float4 u = *(const float4*)&vbase[roff];
            *(float4*)&Vs[k][d4] = u;
        }
        __syncthreads();

        // scores: 4q x 2k per thread
        float s[4][2];
        s[0][0]=0.f;s[0][1]=0.f;s[1][0]=0.f;s[1][1]=0.f;
        s[2][0]=0.f;s[2][1]=0.f;s[3][0]=0.f;s[3][1]=0.f;
        #pragma unroll 8
        for (int d = 0; d < 64; d++) {
            float4 a  = *(const float4*)&Qs[d][ty*4];
            float2 bk = *(const float2*)&Ks[d][tx*2];
            s[0][0] = fmaf(a.x, bk.x, s[0][0]); s[0][1] = fmaf(a.x, bk.y, s[0][1]);
            s[1][0] = fmaf(a.y, bk.x, s[1][0]); s[1][1] = fmaf(a.y, bk.y, s[1][1]);
            s[2][0] = fmaf(a.z, bk.x, s[2][0]); s[2][1] = fmaf(a.z, bk.y, s[2][1]);
            s[3][0] = fmaf(a.w, bk.x, s[3][0]); s[3][1] = fmaf(a.w, bk.y, s[3][1]);
        }

        // causal mask
        const int kg = kt*AK + tx*2;
        #pragma unroll
        for (int i = 0; i < 4; i++) {
            int qg = q0 + ty*4 + i;
            if (kg     > qg) s[i][0] = -1e30f;
            if (kg + 1 > qg) s[i][1] = -1e30f;
        }

        // online softmax (row state replicated across the 16 tx threads)
        #pragma unroll
        for (int i = 0; i < 4; i++) {
            float smax = fmaxf(s[i][0], s[i][1]);
            smax = fmaxf(smax, __shfl_xor_sync(0xffffffffu, smax, 1));
            smax = fmaxf(smax, __shfl_xor_sync(0xffffffffu, smax, 2));
            smax = fmaxf(smax, __shfl_xor_sync(0xffffffffu, smax, 4));
            smax = fmaxf(smax, __shfl_xor_sync(0xffffffffu, smax, 8));
            float mn    = fmaxf(m[i], smax);
            float alpha = __expf(m[i] - mn);
            float p0 = __expf(s[i][0] - mn);
            float p1 = __expf(s[i][1] - mn);
            float ps = p0 + p1;
            ps += __shfl_xor_sync(0xffffffffu, ps, 1);
            ps += __shfl_xor_sync(0xffffffffu, ps, 2);
            ps += __shfl_xor_sync(0xffffffffu, ps, 4);
            ps += __shfl_xor_sync(0xffffffffu, ps, 8);
            l[i] = l[i]*alpha + ps;
            m[i] = mn;
            o[i][0]*=alpha; o[i][1]*=alpha; o[i][2]*=alpha; o[i][3]*=alpha;
            Ps[ty*4+i][tx*2+0] = p0;
            Ps[ty*4+i][tx*2+1] = p1;
        }
        __syncthreads();

        // AV: o[4q][4d] += P[q][k] * V[k][d]
        #pragma unroll 4
        for (int k = 0; k < AK; k++) {
            float4 vv = *(const float4*)&Vs[k][tx*4];
            float a0 = Ps[ty*4+0][k];
            float a1 = Ps[ty*4+1][k];
            float a2 = Ps[ty*4+2][k];
            float a3 = Ps[ty*4+3][k];
            o[0][0]=fmaf(a0,vv.x,o[0][0]); o[0][1]=fmaf(a0,vv.y,o[0][1]); o[0][2]=fmaf(a0,vv.z,o[0][2]); o[0][3]=fmaf(a0,vv.w,o[0][3]);
            o[1][0]=fmaf(a1,vv.x,o[1][0]); o[1][1]=fmaf(a1,vv.y,o[1][1]); o[1][2]=fmaf(a1,vv.z,o[1][2]); o[1][3]=fmaf(a1,vv.w,o[1][3]);
            o[2][0]=fmaf(a2,vv.x,o[2][0]); o[2][1]=fmaf(a2,vv.y,o[2][1]); o[2][2]=fmaf(a2,vv.z,o[2][2]); o[2][3]=fmaf(a2,vv.w,o[2][3]);
            o[3][0]=fmaf(a3,vv.x,o[3][0]); o[3][1]=fmaf(a3,vv.y,o[3][1]); o[3][2]=fmaf(a3,vv.z,o[3][2]); o[3][3]=fmaf(a3,vv.w,o[3][3]);
        }
    }

    // epilogue
    float* yb = y + (size_t)(b*TT)*CC + h*DD;
    #pragma unroll
    for (int i = 0; i < 4; i++) {
        float inv = 1.0f / l[i];
        float4 r;
        r.x = o[i][0]*inv; r.y = o[i][1]*inv;
        r.z = o[i][2]*inv; r.w = o[i][3]*inv;
        *(float4*)&yb[(size_t)(q0+ty*4+i)*CC + tx*4] = r;
    }
}

// ---------------- launch ----------------
extern "C" void kernel_launch(void* const* d_in, const int* in_sizes, int n_in,
                              void* d_out, int out_size)
{
    (void)in_sizes; (void)n_in; (void)out_size;
    const int*   idx     = (const int*)  d_in[0];
    const float* wte     = (const float*)d_in[1];
    const float* wpe     = (const float*)d_in[2];
    const float* ln1w    = (const float*)d_in[3];
    const float* ln1b    = (const float*)d_in[4];
    const float* qkvw    = (const float*)d_in[5];
    const float* qkvb    = (const float*)d_in[6];
    const float* projw   = (const float*)d_in[7];
    const float* projb   = (const float*)d_in[8];
    const float* ln2w    = (const float*)d_in[9];
    const float* ln2b    = (const float*)d_in[10];
    const float* fcw     = (const float*)d_in[11];
    const float* fcb     = (const float*)d_in[12];
    const float* fcprojw = (const float*)d_in[13];
    const float* fcprojb = (const float*)d_in[14];
    const float* lnfw    = (const float*)d_in[15];
    const float* lnfb    = (const float*)d_in[16];
    float* out = (float*)d_out;

    float *x, *ln, *qkv, *att, *act;
    cudaGetSymbolAddress((void**)&x,   g_x);
    cudaGetSymbolAddress((void**)&ln,  g_ln);
    cudaGetSymbolAddress((void**)&qkv, g_qkv);
    cudaGetSymbolAddress((void**)&att, g_att);
    cudaGetSymbolAddress((void**)&act, g_act);

    dim3 thr256(256);

    embed_kernel<<<MROWS, 256>>>(idx, wte, wpe, x);

    for (int l = 0; l < LL; l++) {
        ln_kernel<<<MROWS, 256>>>(x, ln1w + l*CC, ln1b + l*CC, ln);

        gemm_tn<false,false><<<dim3(C3/BN, MROWS/BM), thr256>>>(
            ln, qkvw + (size_t)l*C3*CC, qkvb + (size_t)l*C3, nullptr,
            qkv, MROWS, C3, CC);

        attn_kernel<<<dim3(TT/AQ, HH, BATCH), 256>>>(qkv, att);

        gemm_tn<false,true><<<dim3(CC/BN, MROWS/BM), thr256>>>(
            att, projw + (size_t)l*CC*CC, projb + (size_t)l*CC, x,
            x, MROWS, CC, CC);

        ln_kernel<<<MROWS, 256>>>(x, ln2w + l*CC, ln2b + l*CC, ln);

        gemm_tn<true,false><<<dim3(C4/BN, MROWS/BM), thr256>>>(
            ln, fcw + (size_t)l*C4*CC, fcb + (size_t)l*C4, nullptr,
            act, MROWS, C4, CC);

        gemm_tn<false,true><<<dim3(CC/BN, MROWS/BM), thr256>>>(
            act, fcprojw + (size_t)l*CC*C4, fcprojb + (size_t)l*CC, x,
            x, MROWS, CC, C4);
    }

    ln_kernel<<<MROWS, 256>>>(x, lnfw, lnfb, ln);

    gemm_tn<false,false><<<dim3(VP/BN, MROWS/BM), thr256>>>(
        ln, wte, nullptr, nullptr, out, MROWS, VP, CC);
}

// round 3
// speedup vs baseline: 2.3573x; 1.5309x over previous
#include <cuda_runtime.h>
#include <cuda_bf16.h>
#include <math.h>
#include <stdint.h>

// ---------------- problem constants ----------------
#define BATCH 2
#define TT    1024
#define CC    768
#define HH    12
#define DD    64
#define LL    12
#define MROWS (BATCH*TT)      // 2048
#define C3    (3*CC)          // 2304
#define C4    (4*CC)          // 3072
#define VP    50304

// ---------------- scratch (device globals; no allocation allowed) ----------
__device__ float g_x  [MROWS*CC];
__device__ float g_ln [MROWS*CC];
__device__ float g_qkv[MROWS*C3];
__device__ float g_att[MROWS*CC];
__device__ float g_act[MROWS*C4];

// ---------------- embedding ----------------
__global__ void embed_kernel(const int* __restrict__ idx,
                             const float* __restrict__ wte,
                             const float* __restrict__ wpe,
                             float* __restrict__ x)
{
    int m = blockIdx.x;
    int t = m & (TT-1);
    int tok = idx[m];
    const float* we = wte + (size_t)tok * CC;
    const float* wp = wpe + (size_t)t * CC;
    float* xr = x + (size_t)m * CC;
    for (int c = threadIdx.x; c < CC; c += blockDim.x)
        xr[c] = we[c] + wp[c];
}

// ---------------- layernorm ----------------
__global__ void ln_kernel(const float* __restrict__ x,
                          const float* __restrict__ w,
                          const float* __restrict__ b,
                          float* __restrict__ y)
{
    __shared__ float red[256];
    int row = blockIdx.x;
    int tid = threadIdx.x;
    const float* xr = x + (size_t)row * CC;

    float v0 = xr[tid], v1 = xr[tid+256], v2 = xr[tid+512];
    float local = v0 + v1 + v2;
    red[tid] = local; __syncthreads();
    for (int s = 128; s > 0; s >>= 1) {
        if (tid < s) red[tid] += red[tid+s];
        __syncthreads();
    }
    float mu = red[0] * (1.0f/CC);
    __syncthreads();

    float d0 = v0-mu, d1 = v1-mu, d2 = v2-mu;
    red[tid] = d0*d0 + d1*d1 + d2*d2; __syncthreads();
    for (int s = 128; s > 0; s >>= 1) {
        if (tid < s) red[tid] += red[tid+s];
        __syncthreads();
    }
    float rstd = rsqrtf(red[0] * (1.0f/CC) + 1e-5f);

    float* yr = y + (size_t)row * CC;
    yr[tid]     = d0*rstd*w[tid]     + b[tid];
    yr[tid+256] = d1*rstd*w[tid+256] + b[tid+256];
    yr[tid+512] = d2*rstd*w[tid+512] + b[tid+512];
}

__device__ __forceinline__ float gelu_tanh(float x) {
    float x3 = x*x*x;
    return 0.5f * x * (1.0f + tanhf(0.7978845608028654f * (x + 0.044715f * x3)));
}

// ---------------- bf16 split helpers ----------------
__device__ __forceinline__ void bsplit(float x, float y, uint32_t &hi, uint32_t &lo)
{
    __nv_bfloat16 xh = __float2bfloat16(x);
    __nv_bfloat16 yh = __float2bfloat16(y);
    float xr = x - __bfloat162float(xh);
    float yr = y - __bfloat162float(yh);
    __nv_bfloat162 H; H.x = xh; H.y = yh;
    __nv_bfloat162 L; L.x = __float2bfloat16(xr); L.y = __float2bfloat16(yr);
    hi = *reinterpret_cast<const uint32_t*>(&H);
    lo = *reinterpret_cast<const uint32_t*>(&L);
}

__device__ __forceinline__ void store_tile(uint32_t* hi, uint32_t* lo,
                                           int row, int kc, float4 v)
{
    uint32_t h0,l0,h1,l1;
    bsplit(v.x, v.y, h0, l0);
    bsplit(v.z, v.w, h1, l1);
    int idx = row*12 + (kc>>1);     // idx even -> 8B aligned
    uint2 H; H.x = h0; H.y = h1;
    uint2 L; L.x = l0; L.y = l1;
    *reinterpret_cast<uint2*>(&hi[idx]) = H;
    *reinterpret_cast<uint2*>(&lo[idx]) = L;
}

__device__ __forceinline__ void mma16816(float* d,
    uint32_t a0, uint32_t a1, uint32_t a2, uint32_t a3,
    uint32_t b0, uint32_t b1)
{
    asm volatile(
        "mma.sync.aligned.m16n8k16.row.col.f32.bf16.bf16.f32 "
        "{%0,%1,%2,%3}, {%4,%5,%6,%7}, {%8,%9}, {%0,%1,%2,%3};"
        : "+f"(d[0]), "+f"(d[1]), "+f"(d[2]), "+f"(d[3])
        : "r"(a0), "r"(a1), "r"(a2), "r"(a3), "r"(b0), "r"(b1));
}

// ---------------- split-bf16 tensor-core GEMM: Y = X @ W^T (+bias)(gelu)(+res)
// Tile 128x128, BK=16, 256 threads (8 warps, 2x4 warp grid, 64x32 per warp).
// smem: hi/lo bf16x2 tiles, stride 12 uint32/row (bank-conflict-free for
// the m16n8k16 fragment pattern), double buffered = exactly 48KB.
#define STG 6144   // uint32 per stage (4 arrays x 128*12)

template<bool GELU, bool RES>
__global__ void __launch_bounds__(256)
gemm_tn_bf16(const float* __restrict__ X, const float* __restrict__ W,
             const float* __restrict__ bias, const float* __restrict__ res,
             float* __restrict__ Y, int M, int N, int K)
{
    __shared__ uint32_t SH[2*STG];

    const int tid  = threadIdx.x;
    const int bm   = blockIdx.y * 128;
    const int bn   = blockIdx.x * 128;
    const int lane = tid & 31;
    const int warp = tid >> 5;
    const int wm   = warp & 1;     // 2 warps in M
    const int wn   = warp >> 1;    // 4 warps in N
    const int g    = lane >> 2;
    const int tg   = lane & 3;

    float d[4][4][4];
    #pragma unroll
    for (int i = 0; i < 4; i++)
        #pragma unroll
        for (int j = 0; j < 4; j++) {
            d[i][j][0]=0.f; d[i][j][1]=0.f; d[i][j][2]=0.f; d[i][j][3]=0.f;
        }

    // global tile load mapping: 512 float4 per matrix, 2 per thread
    const int r0 = tid >> 2;           // 0..63
    const int kc = (tid & 3) * 4;      // 0,4,8,12
    const float* Xr1 = X + (size_t)(bm + r0     ) * K + kc;
    const float* Xr2 = X + (size_t)(bm + r0 + 64) * K + kc;
    const float* Wr1 = W + (size_t)(bn + r0     ) * K + kc;
    const float* Wr2 = W + (size_t)(bn + r0 + 64) * K + kc;

    // prologue: stage 0
    {
        float4 a0 = *(const float4*)Xr1;
        float4 a1 = *(const float4*)Xr2;
        float4 b0 = *(const float4*)Wr1;
        float4 b1 = *(const float4*)Wr2;
        uint32_t* base = SH;
        store_tile(base,      base+1536, r0,    kc, a0);
        store_tile(base,      base+1536, r0+64, kc, a1);
        store_tile(base+3072, base+4608, r0,    kc, b0);
        store_tile(base+3072, base+4608, r0+64, kc, b1);
    }
    __syncthreads();

    const int NT = K >> 4;
    for (int t = 0; t < NT; ++t) {
        float4 pa0, pa1, pb0, pb1;
        if (t + 1 < NT) {
            int off = (t+1) * 16;
            pa0 = *(const float4*)(Xr1 + off);
            pa1 = *(const float4*)(Xr2 + off);
            pb0 = *(const float4*)(Wr1 + off);
            pb1 = *(const float4*)(Wr2 + off);
        }

        // ---- compute on buffer t&1 ----
        {
            const uint32_t* base = SH + (t & 1) * STG;
            const uint32_t* Ah = base;
            const uint32_t* Al = base + 1536;
            const uint32_t* Bh = base + 3072;
            const uint32_t* Bl = base + 4608;

            uint32_t ah[4][4], al[4][4], bh[4][2], bl[4][2];
            #pragma unroll
            for (int fm = 0; fm < 4; fm++) {
                int rb = (wm*64 + fm*16 + g)*12 + tg;
                ah[fm][0]=Ah[rb];    ah[fm][1]=Ah[rb+96];
                ah[fm][2]=Ah[rb+4];  ah[fm][3]=Ah[rb+100];
                al[fm][0]=Al[rb];    al[fm][1]=Al[rb+96];
                al[fm][2]=Al[rb+4];  al[fm][3]=Al[rb+100];
            }
            #pragma unroll
            for (int fn = 0; fn < 4; fn++) {
                int rb = (wn*32 + fn*8 + g)*12 + tg;
                bh[fn][0]=Bh[rb]; bh[fn][1]=Bh[rb+4];
                bl[fn][0]=Bl[rb]; bl[fn][1]=Bl[rb+4];
            }
            #pragma unroll
            for (int fm = 0; fm < 4; fm++)
                #pragma unroll
                for (int fn = 0; fn < 4; fn++) {
                    mma16816(d[fm][fn], ah[fm][0],ah[fm][1],ah[fm][2],ah[fm][3],
                             bh[fn][0], bh[fn][1]);
                    mma16816(d[fm][fn], al[fm][0],al[fm][1],al[fm][2],al[fm][3],
                             bh[fn][0], bh[fn][1]);
                    mma16816(d[fm][fn], ah[fm][0],ah[fm][1],ah[fm][2],ah[fm][3],
                             bl[fn][0], bl[fn][1]);
                }
        }

        if (t + 1 < NT) {
            uint32_t* base = SH + ((t+1) & 1) * STG;
            store_tile(base,      base+1536, r0,    kc, pa0);
            store_tile(base,      base+1536, r0+64, kc, pa1);
            store_tile(base+3072, base+4608, r0,    kc, pb0);
            store_tile(base+3072, base+4608, r0+64, kc, pb1);
        }
        __syncthreads();
    }

    // ---- epilogue ----
    #pragma unroll
    for (int fm = 0; fm < 4; fm++) {
        int mrow = bm + wm*64 + fm*16 + g;
        #pragma unroll
        for (int half = 0; half < 2; half++) {
            int m = mrow + half*8;
            float* yr = Y + (size_t)m * N;
            #pragma unroll
            for (int fn = 0; fn < 4; fn++) {
                int n0 = bn + wn*32 + fn*8 + tg*2;
                float v0 = d[fm][fn][half*2+0];
                float v1 = d[fm][fn][half*2+1];
                if (bias) { v0 += bias[n0]; v1 += bias[n0+1]; }
                if (GELU) { v0 = gelu_tanh(v0); v1 = gelu_tanh(v1); }
                if (RES) {
                    const float* rr = res + (size_t)m * N;
                    float2 rv = *(const float2*)&rr[n0];
                    v0 += rv.x; v1 += rv.y;
                }
                float2 o2; o2.x = v0; o2.y = v1;
                *(float2*)&yr[n0] = o2;
            }
        }
    }
}

// ---------------- flash attention: 64 queries/block, 32-key tiles ----------------
#define AQ 64
#define AK 32

__global__ void __launch_bounds__(256)
attn_kernel(const float* __restrict__ qkv, float* __restrict__ y)
{
    __shared__ float Qs[64][68];
    __shared__ float Ks[64][34];
    __shared__ float Vs[AK][68];
    __shared__ float Ps[64][36];

    const int qt  = blockIdx.x;
    const int h   = blockIdx.y;
    const int b   = blockIdx.z;
    const int tid = threadIdx.x;
    const int tx  = tid & 15;
    const int ty  = tid >> 4;
    const int q0  = qt * AQ;

    const float* qbase = qkv + (size_t)(b*TT)*C3 + h*DD;
    const float* kbase = qbase + CC;
    const float* vbase = qbase + 2*CC;

    #pragma unroll
    for (int i = 0; i < 4; i++) {
        int v  = tid + i*256;
        int q  = v >> 4;
        int d4 = (v & 15) * 4;
        float4 t = *(const float4*)&qbase[(size_t)(q0+q)*C3 + d4];
        Qs[d4+0][q] = t.x*0.125f; Qs[d4+1][q] = t.y*0.125f;
        Qs[d4+2][q] = t.z*0.125f; Qs[d4+3][q] = t.w*0.125f;
    }

    float o[4][4];
    float m[4], l[4];
    #pragma unroll
    for (int i = 0; i < 4; i++) {
        m[i] = -1e30f; l[i] = 0.0f;
        o[i][0]=0.f; o[i][1]=0.f; o[i][2]=0.f; o[i][3]=0.f;
    }

    const int ntiles = (q0 + AQ) / AK;
    for (int kt = 0; kt < ntiles; kt++) {
        __syncthreads();

        #pragma unroll
        for (int i = 0; i < 2; i++) {
            int v  = tid + i*256;
            int k  = v >> 4;
            int d4 = (v & 15) * 4;
            size_t roff = (size_t)(kt*AK + k)*C3 + d4;
            float4 t = *(const float4*)&kbase[roff];
            Ks[d4+0][k]=t.x; Ks[d4+1][k]=t.y; Ks[d4+2][k]=t.z; Ks[d4+3][k]=t.w;
            float4 u = *(const float4*)&vbase[roff];
            *(float4*)&Vs[k][d4] = u;
        }
        __syncthreads();

        float s[4][2];
        s[0][0]=0.f;s[0][1]=0.f;s[1][0]=0.f;s[1][1]=0.f;
        s[2][0]=0.f;s[2][1]=0.f;s[3][0]=0.f;s[3][1]=0.f;
        #pragma unroll 8
        for (int dd = 0; dd < 64; dd++) {
            float4 a  = *(const float4*)&Qs[dd][ty*4];
            float2 bk = *(const float2*)&Ks[dd][tx*2];
            s[0][0] = fmaf(a.x, bk.x, s[0][0]); s[0][1] = fmaf(a.x, bk.y, s[0][1]);
            s[1][0] = fmaf(a.y, bk.x, s[1][0]); s[1][1] = fmaf(a.y, bk.y, s[1][1]);
            s[2][0] = fmaf(a.z, bk.x, s[2][0]); s[2][1] = fmaf(a.z, bk.y, s[2][1]);
            s[3][0] = fmaf(a.w, bk.x, s[3][0]); s[3][1] = fmaf(a.w, bk.y, s[3][1]);
        }

        const int kg = kt*AK + tx*2;
        #pragma unroll
        for (int i = 0; i < 4; i++) {
            int qg = q0 + ty*4 + i;
            if (kg     > qg) s[i][0] = -1e30f;
            if (kg + 1 > qg) s[i][1] = -1e30f;
        }

        #pragma unroll
        for (int i = 0; i < 4; i++) {
            float smax = fmaxf(s[i][0], s[i][1]);
            smax = fmaxf(smax, __shfl_xor_sync(0xffffffffu, smax, 1));
            smax = fmaxf(smax, __shfl_xor_sync(0xffffffffu, smax, 2));
            smax = fmaxf(smax, __shfl_xor_sync(0xffffffffu, smax, 4));
            smax = fmaxf(smax, __shfl_xor_sync(0xffffffffu, smax, 8));
            float mn    = fmaxf(m[i], smax);
            float alpha = __expf(m[i] - mn);
            float p0 = __expf(s[i][0] - mn);
            float p1 = __expf(s[i][1] - mn);
            float ps = p0 + p1;
            ps += __shfl_xor_sync(0xffffffffu, ps, 1);
            ps += __shfl_xor_sync(0xffffffffu, ps, 2);
            ps += __shfl_xor_sync(0xffffffffu, ps, 4);
            ps += __shfl_xor_sync(0xffffffffu, ps, 8);
            l[i] = l[i]*alpha + ps;
            m[i] = mn;
            o[i][0]*=alpha; o[i][1]*=alpha; o[i][2]*=alpha; o[i][3]*=alpha;
            Ps[ty*4+i][tx*2+0] = p0;
            Ps[ty*4+i][tx*2+1] = p1;
        }
        __syncthreads();

        #pragma unroll 4
        for (int k = 0; k < AK; k++) {
            float4 vv = *(const float4*)&Vs[k][tx*4];
            float a0 = Ps[ty*4+0][k];
            float a1 = Ps[ty*4+1][k];
            float a2 = Ps[ty*4+2][k];
            float a3 = Ps[ty*4+3][k];
            o[0][0]=fmaf(a0,vv.x,o[0][0]); o[0][1]=fmaf(a0,vv.y,o[0][1]); o[0][2]=fmaf(a0,vv.z,o[0][2]); o[0][3]=fmaf(a0,vv.w,o[0][3]);
            o[1][0]=fmaf(a1,vv.x,o[1][0]); o[1][1]=fmaf(a1,vv.y,o[1][1]); o[1][2]=fmaf(a1,vv.z,o[1][2]); o[1][3]=fmaf(a1,vv.w,o[1][3]);
            o[2][0]=fmaf(a2,vv.x,o[2][0]); o[2][1]=fmaf(a2,vv.y,o[2][1]); o[2][2]=fmaf(a2,vv.z,o[2][2]); o[2][3]=fmaf(a2,vv.w,o[2][3]);
            o[3][0]=fmaf(a3,vv.x,o[3][0]); o[3][1]=fmaf(a3,vv.y,o[3][1]); o[3][2]=fmaf(a3,vv.z,o[3][2]); o[3][3]=fmaf(a3,vv.w,o[3][3]);
        }
    }

    float* yb = y + (size_t)(b*TT)*CC + h*DD;
    #pragma unroll
    for (int i = 0; i < 4; i++) {
        float inv = 1.0f / l[i];
        float4 r;
        r.x = o[i][0]*inv; r.y = o[i][1]*inv;
        r.z = o[i][2]*inv; r.w = o[i][3]*inv;
        *(float4*)&yb[(size_t)(q0+ty*4+i)*CC + tx*4] = r;
    }
}

// ---------------- launch ----------------
extern "C" void kernel_launch(void* const* d_in, const int* in_sizes, int n_in,
                              void* d_out, int out_size)
{
    (void)in_sizes; (void)n_in; (void)out_size;
    const int*   idx     = (const int*)  d_in[0];
    const float* wte     = (const float*)d_in[1];
    const float* wpe     = (const float*)d_in[2];
    const float* ln1w    = (const float*)d_in[3];
    const float* ln1b    = (const float*)d_in[4];
    const float* qkvw    = (const float*)d_in[5];
    const float* qkvb    = (const float*)d_in[6];
    const float* projw   = (const float*)d_in[7];
    const float* projb   = (const float*)d_in[8];
    const float* ln2w    = (const float*)d_in[9];
    const float* ln2b    = (const float*)d_in[10];
    const float* fcw     = (const float*)d_in[11];
    const float* fcb     = (const float*)d_in[12];
    const float* fcprojw = (const float*)d_in[13];
    const float* fcprojb = (const float*)d_in[14];
    const float* lnfw    = (const float*)d_in[15];
    const float* lnfb    = (const float*)d_in[16];
    float* out = (float*)d_out;

    float *x, *ln, *qkv, *att, *act;
    cudaGetSymbolAddress((void**)&x,   g_x);
    cudaGetSymbolAddress((void**)&ln,  g_ln);
    cudaGetSymbolAddress((void**)&qkv, g_qkv);
    cudaGetSymbolAddress((void**)&att, g_att);
    cudaGetSymbolAddress((void**)&act, g_act);

    dim3 thr256(256);

    embed_kernel<<<MROWS, 256>>>(idx, wte, wpe, x);

    for (int l = 0; l < LL; l++) {
        ln_kernel<<<MROWS, 256>>>(x, ln1w + l*CC, ln1b + l*CC, ln);

        gemm_tn_bf16<false,false><<<dim3(C3/128, MROWS/128), thr256>>>(
            ln, qkvw + (size_t)l*C3*CC, qkvb + (size_t)l*C3, nullptr,
            qkv, MROWS, C3, CC);

        attn_kernel<<<dim3(TT/AQ, HH, BATCH), 256>>>(qkv, att);

        gemm_tn_bf16<false,true><<<dim3(CC/128, MROWS/128), thr256>>>(
            att, projw + (size_t)l*CC*CC, projb + (size_t)l*CC, x,
            x, MROWS, CC, CC);

        ln_kernel<<<MROWS, 256>>>(x, ln2w + l*CC, ln2b + l*CC, ln);

        gemm_tn_bf16<true,false><<<dim3(C4/128, MROWS/128), thr256>>>(
            ln, fcw + (size_t)l*C4*CC, fcb + (size_t)l*C4, nullptr,
            act, MROWS, C4, CC);

        gemm_tn_bf16<false,true><<<dim3(CC/128, MROWS/128), thr256>>>(
            act, fcprojw + (size_t)l*CC*C4, fcprojb + (size_t)l*CC, x,
            x, MROWS, CC, C4);
    }

    ln_kernel<<<MROWS, 256>>>(x, lnfw, lnfb, ln);

    gemm_tn_bf16<false,false><<<dim3(VP/128, MROWS/128), thr256>>>(
        ln, wte, nullptr, nullptr, out, MROWS, VP, CC);
}

// round 4
// speedup vs baseline: 2.5311x; 1.0737x over previous
#include <cuda_runtime.h>
#include <cuda_bf16.h>
#include <math.h>
#include <stdint.h>

// ---------------- problem constants ----------------
#define BATCH 2
#define TT    1024
#define CC    768
#define HH    12
#define DD    64
#define LL    12
#define MROWS (BATCH*TT)      // 2048
#define C3    (3*CC)          // 2304
#define C4    (4*CC)          // 3072
#define VP    50304

// ---------------- scratch (device globals) ----------
__device__ float g_x  [MROWS*CC];
__device__ float g_qkv[MROWS*C3];

// split-bf16 activations
__device__ __nv_bfloat16 g_ln_h [MROWS*CC],  g_ln_l [MROWS*CC];
__device__ __nv_bfloat16 g_att_h[MROWS*CC],  g_att_l[MROWS*CC];
__device__ __nv_bfloat16 g_act_h[MROWS*C4],  g_act_l[MROWS*C4];

// split-bf16 weights (converted once per launch)
__device__ __nv_bfloat16 g_qkvw_h [(size_t)LL*C3*CC], g_qkvw_l [(size_t)LL*C3*CC];
__device__ __nv_bfloat16 g_projw_h[(size_t)LL*CC*CC], g_projw_l[(size_t)LL*CC*CC];
__device__ __nv_bfloat16 g_fcw_h  [(size_t)LL*C4*CC], g_fcw_l  [(size_t)LL*C4*CC];
__device__ __nv_bfloat16 g_fcpw_h [(size_t)LL*CC*C4], g_fcpw_l [(size_t)LL*CC*C4];
__device__ __nv_bfloat16 g_wte_h  [(size_t)VP*CC],    g_wte_l  [(size_t)VP*CC];

// ---------------- helpers ----------------
__device__ __forceinline__ uint32_t pack2(float x, float y, uint32_t &lo)
{
    __nv_bfloat16 xh = __float2bfloat16(x);
    __nv_bfloat16 yh = __float2bfloat16(y);
    __nv_bfloat162 H; H.x = xh; H.y = yh;
    __nv_bfloat162 L; L.x = __float2bfloat16(x - __bfloat162float(xh));
    L.y = __float2bfloat16(y - __bfloat162float(yh));
    lo = *reinterpret_cast<const uint32_t*>(&L);
    return *reinterpret_cast<const uint32_t*>(&H);
}

// ---------------- weight pre-split ----------------
__global__ void split_kernel(const float* __restrict__ s,
                             __nv_bfloat16* __restrict__ h,
                             __nv_bfloat16* __restrict__ l, long n4)
{
    long stride = (long)gridDim.x * blockDim.x;
    for (long i = (long)blockIdx.x * blockDim.x + threadIdx.x; i < n4; i += stride) {
        float4 v = ((const float4*)s)[i];
        uint2 H, L;
        H.x = pack2(v.x, v.y, L.x);
        H.y = pack2(v.z, v.w, L.y);
        ((uint2*)h)[i] = H;
        ((uint2*)l)[i] = L;
    }
}

// ---------------- embedding ----------------
__global__ void embed_kernel(const int* __restrict__ idx,
                             const float* __restrict__ wte,
                             const float* __restrict__ wpe,
                             float* __restrict__ x)
{
    int m = blockIdx.x;
    int t = m & (TT-1);
    int tok = idx[m];
    const float* we = wte + (size_t)tok * CC;
    const float* wp = wpe + (size_t)t * CC;
    float* xr = x + (size_t)m * CC;
    for (int c = threadIdx.x; c < CC; c += blockDim.x)
        xr[c] = we[c] + wp[c];
}

// ---------------- layernorm -> split bf16 ----------------
__global__ void ln_kernel(const float* __restrict__ x,
                          const float* __restrict__ w,
                          const float* __restrict__ b,
                          __nv_bfloat16* __restrict__ yh,
                          __nv_bfloat16* __restrict__ yl)
{
    __shared__ float red[256];
    int row = blockIdx.x;
    int tid = threadIdx.x;
    const float* xr = x + (size_t)row * CC;

    float v0 = xr[tid], v1 = xr[tid+256], v2 = xr[tid+512];
    float local = v0 + v1 + v2;
    red[tid] = local; __syncthreads();
    for (int s = 128; s > 0; s >>= 1) {
        if (tid < s) red[tid] += red[tid+s];
        __syncthreads();
    }
    float mu = red[0] * (1.0f/CC);
    __syncthreads();

    float d0 = v0-mu, d1 = v1-mu, d2 = v2-mu;
    red[tid] = d0*d0 + d1*d1 + d2*d2; __syncthreads();
    for (int s = 128; s > 0; s >>= 1) {
        if (tid < s) red[tid] += red[tid+s];
        __syncthreads();
    }
    float rstd = rsqrtf(red[0] * (1.0f/CC) + 1e-5f);

    size_t base = (size_t)row * CC;
    #pragma unroll
    for (int j = 0; j < 3; j++) {
        int c = tid + j*256;
        float v = (j==0?d0:(j==1?d1:d2))*rstd*w[c] + b[c];
        __nv_bfloat16 hv = __float2bfloat16(v);
        yh[base+c] = hv;
        yl[base+c] = __float2bfloat16(v - __bfloat162float(hv));
    }
}

__device__ __forceinline__ float gelu_tanh(float x) {
    float x3 = x*x*x;
    return 0.5f * x * (1.0f + tanhf(0.7978845608028654f * (x + 0.044715f * x3)));
}

__device__ __forceinline__ void mma16816(float* d,
    uint32_t a0, uint32_t a1, uint32_t a2, uint32_t a3,
    uint32_t b0, uint32_t b1)
{
    asm volatile(
        "mma.sync.aligned.m16n8k16.row.col.f32.bf16.bf16.f32 "
        "{%0,%1,%2,%3}, {%4,%5,%6,%7}, {%8,%9}, {%0,%1,%2,%3};"
        : "+f"(d[0]), "+f"(d[1]), "+f"(d[2]), "+f"(d[3])
        : "r"(a0), "r"(a1), "r"(a2), "r"(a3), "r"(b0), "r"(b1));
}

// ---------------- split-bf16 tensor-core GEMM ----------------
// Y = X @ W^T (+bias)(gelu)(+res). Inputs pre-split bf16 hi/lo.
// Tile 128x128, BK=16, 256 threads (8 warps, 2x4, 64x32 each).
// smem stride 12 u32/row (conflict-free), double buffered = 48KB.
#define STG 6144

template<bool GELU, bool RES, bool OUTSPLIT>
__global__ void __launch_bounds__(256)
gemm_tn_bf16(const __nv_bfloat16* __restrict__ Xh, const __nv_bfloat16* __restrict__ Xl,
             const __nv_bfloat16* __restrict__ Wh, const __nv_bfloat16* __restrict__ Wl,
             const float* __restrict__ bias, const float* __restrict__ res,
             float* __restrict__ Y,
             __nv_bfloat16* __restrict__ Yh, __nv_bfloat16* __restrict__ Yl,
             int M, int N, int K)
{
    __shared__ uint32_t SH[2*STG];

    const int tid  = threadIdx.x;
    const int bm   = blockIdx.y * 128;
    const int bn   = blockIdx.x * 128;
    const int lane = tid & 31;
    const int warp = tid >> 5;
    const int wm   = warp & 1;
    const int wn   = warp >> 1;
    const int g    = lane >> 2;
    const int tg   = lane & 3;

    float d[4][4][4];
    #pragma unroll
    for (int i = 0; i < 4; i++)
        #pragma unroll
        for (int j = 0; j < 4; j++) {
            d[i][j][0]=0.f; d[i][j][1]=0.f; d[i][j][2]=0.f; d[i][j][3]=0.f;
        }

    // global load mapping: thread -> one uint4 (8 bf16) per array per stage
    const int row = tid >> 1;          // 0..127
    const int hc  = (tid & 1) * 4;     // u32 col 0 or 4
    const int Ku  = K >> 1;            // u32 per row
    const uint32_t* xh32 = (const uint32_t*)Xh + (size_t)(bm + row)*Ku + hc;
    const uint32_t* xl32 = (const uint32_t*)Xl + (size_t)(bm + row)*Ku + hc;
    const uint32_t* wh32 = (const uint32_t*)Wh + (size_t)(bn + row)*Ku + hc;
    const uint32_t* wl32 = (const uint32_t*)Wl + (size_t)(bn + row)*Ku + hc;
    const int sidx = row*12 + hc;

    // prologue: stage 0
    {
        uint4 a = *(const uint4*)xh32;
        uint4 b = *(const uint4*)xl32;
        uint4 c = *(const uint4*)wh32;
        uint4 e = *(const uint4*)wl32;
        *(uint4*)&SH[sidx       ] = a;
        *(uint4*)&SH[sidx + 1536] = b;
        *(uint4*)&SH[sidx + 3072] = c;
        *(uint4*)&SH[sidx + 4608] = e;
    }
    __syncthreads();

    const int NT = K >> 4;
    for (int t = 0; t < NT; ++t) {
        uint4 pa, pb, pc, pe;
        if (t + 1 < NT) {
            int off = (t+1) * 8;
            pa = *(const uint4*)(xh32 + off);
            pb = *(const uint4*)(xl32 + off);
            pc = *(const uint4*)(wh32 + off);
            pe = *(const uint4*)(wl32 + off);
        }

        {
            const uint32_t* base = SH + (t & 1) * STG;
            const uint32_t* Ah = base;
            const uint32_t* Al = base + 1536;
            const uint32_t* Bh = base + 3072;
            const uint32_t* Bl = base + 4608;

            uint32_t ah[4][4], al[4][4], bh[4][2], bl[4][2];
            #pragma unroll
            for (int fm = 0; fm < 4; fm++) {
                int rb = (wm*64 + fm*16 + g)*12 + tg;
                ah[fm][0]=Ah[rb];    ah[fm][1]=Ah[rb+96];
                ah[fm][2]=Ah[rb+4];  ah[fm][3]=Ah[rb+100];
                al[fm][0]=Al[rb];    al[fm][1]=Al[rb+96];
                al[fm][2]=Al[rb+4];  al[fm][3]=Al[rb+100];
            }
            #pragma unroll
            for (int fn = 0; fn < 4; fn++) {
                int rb = (wn*32 + fn*8 + g)*12 + tg;
                bh[fn][0]=Bh[rb]; bh[fn][1]=Bh[rb+4];
                bl[fn][0]=Bl[rb]; bl[fn][1]=Bl[rb+4];
            }
            #pragma unroll
            for (int fm = 0; fm < 4; fm++)
                #pragma unroll
                for (int fn = 0; fn < 4; fn++) {
                    mma16816(d[fm][fn], ah[fm][0],ah[fm][1],ah[fm][2],ah[fm][3],
                             bh[fn][0], bh[fn][1]);
                    mma16816(d[fm][fn], al[fm][0],al[fm][1],al[fm][2],al[fm][3],
                             bh[fn][0], bh[fn][1]);
                    mma16816(d[fm][fn], ah[fm][0],ah[fm][1],ah[fm][2],ah[fm][3],
                             bl[fn][0], bl[fn][1]);
                }
        }

        if (t + 1 < NT) {
            uint32_t* base = SH + ((t+1) & 1) * STG;
            *(uint4*)&base[sidx       ] = pa;
            *(uint4*)&base[sidx + 1536] = pb;
            *(uint4*)&base[sidx + 3072] = pc;
            *(uint4*)&base[sidx + 4608] = pe;
        }
        __syncthreads();
    }

    // ---- epilogue ----
    #pragma unroll
    for (int fm = 0; fm < 4; fm++) {
        int mrow = bm + wm*64 + fm*16 + g;
        #pragma unroll
        for (int half = 0; half < 2; half++) {
            int m = mrow + half*8;
            #pragma unroll
            for (int fn = 0; fn < 4; fn++) {
                int n0 = bn + wn*32 + fn*8 + tg*2;
                float v0 = d[fm][fn][half*2+0];
                float v1 = d[fm][fn][half*2+1];
                if (bias) { v0 += bias[n0]; v1 += bias[n0+1]; }
                if (GELU) { v0 = gelu_tanh(v0); v1 = gelu_tanh(v1); }
                if (RES) {
                    const float* rr = res + (size_t)m * N;
                    float2 rv = *(const float2*)&rr[n0];
                    v0 += rv.x; v1 += rv.y;
                }
                if (OUTSPLIT) {
                    uint32_t lo;
                    uint32_t hi = pack2(v0, v1, lo);
                    *(uint32_t*)&Yh[(size_t)m*N + n0] = hi;
                    *(uint32_t*)&Yl[(size_t)m*N + n0] = lo;
                } else {
                    float2 o2; o2.x = v0; o2.y = v1;
                    *(float2*)&Y[(size_t)m*N + n0] = o2;
                }
            }
        }
    }
}

// ---------------- flash attention: 64 q/block, 32-key tiles, split-bf16 out ----
#define AQ 64
#define AK 32

__global__ void __launch_bounds__(256)
attn_kernel(const float* __restrict__ qkv,
            __nv_bfloat16* __restrict__ yh, __nv_bfloat16* __restrict__ yl)
{
    __shared__ float Qs[64][68];
    __shared__ float Ks[64][34];
    __shared__ float Vs[AK][68];
    __shared__ float Ps[64][36];

    const int qt  = gridDim.x - 1 - blockIdx.x;   // heavy tiles first
    const int h   = blockIdx.y;
    const int b   = blockIdx.z;
    const int tid = threadIdx.x;
    const int tx  = tid & 15;
    const int ty  = tid >> 4;
    const int q0  = qt * AQ;

    const float* qbase = qkv + (size_t)(b*TT)*C3 + h*DD;
    const float* kbase = qbase + CC;
    const float* vbase = qbase + 2*CC;

    #pragma unroll
    for (int i = 0; i < 4; i++) {
        int v  = tid + i*256;
        int q  = v >> 4;
        int d4 = (v & 15) * 4;
        float4 t = *(const float4*)&qbase[(size_t)(q0+q)*C3 + d4];
        Qs[d4+0][q] = t.x*0.125f; Qs[d4+1][q] = t.y*0.125f;
        Qs[d4+2][q] = t.z*0.125f; Qs[d4+3][q] = t.w*0.125f;
    }

    float o[4][4];
    float m[4], l[4];
    #pragma unroll
    for (int i = 0; i < 4; i++) {
        m[i] = -1e30f; l[i] = 0.0f;
        o[i][0]=0.f; o[i][1]=0.f; o[i][2]=0.f; o[i][3]=0.f;
    }

    const int ntiles = (q0 + AQ) / AK;
    for (int kt = 0; kt < ntiles; kt++) {
        __syncthreads();

        #pragma unroll
        for (int i = 0; i < 2; i++) {
            int v  = tid + i*256;
            int k  = v >> 4;
            int d4 = (v & 15) * 4;
            size_t roff = (size_t)(kt*AK + k)*C3 + d4;
            float4 t = *(const float4*)&kbase[roff];
            Ks[d4+0][k]=t.x; Ks[d4+1][k]=t.y; Ks[d4+2][k]=t.z; Ks[d4+3][k]=t.w;
            float4 u = *(const float4*)&vbase[roff];
            *(float4*)&Vs[k][d4] = u;
        }
        __syncthreads();

        float s[4][2];
        s[0][0]=0.f;s[0][1]=0.f;s[1][0]=0.f;s[1][1]=0.f;
        s[2][0]=0.f;s[2][1]=0.f;s[3][0]=0.f;s[3][1]=0.f;
        #pragma unroll 8
        for (int dd = 0; dd < 64; dd++) {
            float4 a  = *(const float4*)&Qs[dd][ty*4];
            float2 bk = *(const float2*)&Ks[dd][tx*2];
            s[0][0] = fmaf(a.x, bk.x, s[0][0]); s[0][1] = fmaf(a.x, bk.y, s[0][1]);
            s[1][0] = fmaf(a.y, bk.x, s[1][0]); s[1][1] = fmaf(a.y, bk.y, s[1][1]);
            s[2][0] = fmaf(a.z, bk.x, s[2][0]); s[2][1] = fmaf(a.z, bk.y, s[2][1]);
            s[3][0] = fmaf(a.w, bk.x, s[3][0]); s[3][1] = fmaf(a.w, bk.y, s[3][1]);
        }

        const int kg = kt*AK + tx*2;
        #pragma unroll
        for (int i = 0; i < 4; i++) {
            int qg = q0 + ty*4 + i;
            if (kg     > qg) s[i][0] = -1e30f;
            if (kg + 1 > qg) s[i][1] = -1e30f;
        }

        #pragma unroll
        for (int i = 0; i < 4; i++) {
            float smax = fmaxf(s[i][0], s[i][1]);
            smax = fmaxf(smax, __shfl_xor_sync(0xffffffffu, smax, 1));
            smax = fmaxf(smax, __shfl_xor_sync(0xffffffffu, smax, 2));
            smax = fmaxf(smax, __shfl_xor_sync(0xffffffffu, smax, 4));
            smax = fmaxf(smax, __shfl_xor_sync(0xffffffffu, smax, 8));
            float mn    = fmaxf(m[i], smax);
            float alpha = __expf(m[i] - mn);
            float p0 = __expf(s[i][0] - mn);
            float p1 = __expf(s[i][1] - mn);
            float ps = p0 + p1;
            ps += __shfl_xor_sync(0xffffffffu, ps, 1);
            ps += __shfl_xor_sync(0xffffffffu, ps, 2);
            ps += __shfl_xor_sync(0xffffffffu, ps, 4);
            ps += __shfl_xor_sync(0xffffffffu, ps, 8);
            l[i] = l[i]*alpha + ps;
            m[i] = mn;
            o[i][0]*=alpha; o[i][1]*=alpha; o[i][2]*=alpha; o[i][3]*=alpha;
            Ps[ty*4+i][tx*2+0] = p0;
            Ps[ty*4+i][tx*2+1] = p1;
        }
        __syncthreads();

        #pragma unroll 4
        for (int k = 0; k < AK; k++) {
            float4 vv = *(const float4*)&Vs[k][tx*4];
            float a0 = Ps[ty*4+0][k];
            float a1 = Ps[ty*4+1][k];
            float a2 = Ps[ty*4+2][k];
            float a3 = Ps[ty*4+3][k];
            o[0][0]=fmaf(a0,vv.x,o[0][0]); o[0][1]=fmaf(a0,vv.y,o[0][1]); o[0][2]=fmaf(a0,vv.z,o[0][2]); o[0][3]=fmaf(a0,vv.w,o[0][3]);
            o[1][0]=fmaf(a1,vv.x,o[1][0]); o[1][1]=fmaf(a1,vv.y,o[1][1]); o[1][2]=fmaf(a1,vv.z,o[1][2]); o[1][3]=fmaf(a1,vv.w,o[1][3]);
            o[2][0]=fmaf(a2,vv.x,o[2][0]); o[2][1]=fmaf(a2,vv.y,o[2][1]); o[2][2]=fmaf(a2,vv.z,o[2][2]); o[2][3]=fmaf(a2,vv.w,o[2][3]);
            o[3][0]=fmaf(a3,vv.x,o[3][0]); o[3][1]=fmaf(a3,vv.y,o[3][1]); o[3][2]=fmaf(a3,vv.z,o[3][2]); o[3][3]=fmaf(a3,vv.w,o[3][3]);
        }
    }

    #pragma unroll
    for (int i = 0; i < 4; i++) {
        float inv = 1.0f / l[i];
        size_t oidx = (size_t)(b*TT + q0 + ty*4 + i)*CC + h*DD + tx*4;
        uint2 H, L;
        H.x = pack2(o[i][0]*inv, o[i][1]*inv, L.x);
        H.y = pack2(o[i][2]*inv, o[i][3]*inv, L.y);
        *(uint2*)&yh[oidx] = H;
        *(uint2*)&yl[oidx] = L;
    }
}

// ---------------- launch ----------------
extern "C" void kernel_launch(void* const* d_in, const int* in_sizes, int n_in,
                              void* d_out, int out_size)
{
    (void)in_sizes; (void)n_in; (void)out_size;
    const int*   idx     = (const int*)  d_in[0];
    const float* wte     = (const float*)d_in[1];
    const float* wpe     = (const float*)d_in[2];
    const float* ln1w    = (const float*)d_in[3];
    const float* ln1b    = (const float*)d_in[4];
    const float* qkvw    = (const float*)d_in[5];
    const float* qkvb    = (const float*)d_in[6];
    const float* projw   = (const float*)d_in[7];
    const float* projb   = (const float*)d_in[8];
    const float* ln2w    = (const float*)d_in[9];
    const float* ln2b    = (const float*)d_in[10];
    const float* fcw     = (const float*)d_in[11];
    const float* fcb     = (const float*)d_in[12];
    const float* fcprojw = (const float*)d_in[13];
    const float* fcprojb = (const float*)d_in[14];
    const float* lnfw    = (const float*)d_in[15];
    const float* lnfb    = (const float*)d_in[16];
    float* out = (float*)d_out;

    float *x, *qkv;
    __nv_bfloat16 *lnh, *lnl, *atth, *attl, *acth, *actl;
    __nv_bfloat16 *qkvwh, *qkvwl, *projwh, *projwl, *fcwh, *fcwl, *fcpwh, *fcpwl, *wteh, *wtel;
    cudaGetSymbolAddress((void**)&x,    g_x);
    cudaGetSymbolAddress((void**)&qkv,  g_qkv);
    cudaGetSymbolAddress((void**)&lnh,  g_ln_h);   cudaGetSymbolAddress((void**)&lnl,  g_ln_l);
    cudaGetSymbolAddress((void**)&atth, g_att_h);  cudaGetSymbolAddress((void**)&attl, g_att_l);
    cudaGetSymbolAddress((void**)&acth, g_act_h);  cudaGetSymbolAddress((void**)&actl, g_act_l);
    cudaGetSymbolAddress((void**)&qkvwh, g_qkvw_h); cudaGetSymbolAddress((void**)&qkvwl, g_qkvw_l);
    cudaGetSymbolAddress((void**)&projwh,g_projw_h);cudaGetSymbolAddress((void**)&projwl,g_projw_l);
    cudaGetSymbolAddress((void**)&fcwh, g_fcw_h);  cudaGetSymbolAddress((void**)&fcwl, g_fcw_l);
    cudaGetSymbolAddress((void**)&fcpwh,g_fcpw_h); cudaGetSymbolAddress((void**)&fcpwl,g_fcpw_l);
    cudaGetSymbolAddress((void**)&wteh, g_wte_h);  cudaGetSymbolAddress((void**)&wtel, g_wte_l);

    // pre-split all weights to bf16 hi/lo
    const int SB = 1184;  // 8 per SM
    split_kernel<<<SB, 256>>>(qkvw,    qkvwh,  qkvwl,  (long)LL*C3*CC/4);
    split_kernel<<<SB, 256>>>(projw,   projwh, projwl, (long)LL*CC*CC/4);
    split_kernel<<<SB, 256>>>(fcw,     fcwh,   fcwl,   (long)LL*C4*CC/4);
    split_kernel<<<SB, 256>>>(fcprojw, fcpwh,  fcpwl,  (long)LL*CC*C4/4);
    split_kernel<<<SB, 256>>>(wte,     wteh,   wtel,   (long)VP*CC/4);

    dim3 thr256(256);

    embed_kernel<<<MROWS, 256>>>(idx, wte, wpe, x);

    for (int l = 0; l < LL; l++) {
        ln_kernel<<<MROWS, 256>>>(x, ln1w + l*CC, ln1b + l*CC, lnh, lnl);

        gemm_tn_bf16<false,false,false><<<dim3(C3/128, MROWS/128), thr256>>>(
            lnh, lnl, qkvwh + (size_t)l*C3*CC, qkvwl + (size_t)l*C3*CC,
            qkvb + (size_t)l*C3, nullptr, qkv, nullptr, nullptr, MROWS, C3, CC);

        attn_kernel<<<dim3(TT/AQ, HH, BATCH), 256>>>(qkv, atth, attl);

        gemm_tn_bf16<false,true,false><<<dim3(CC/128, MROWS/128), thr256>>>(
            atth, attl, projwh + (size_t)l*CC*CC, projwl + (size_t)l*CC*CC,
            projb + (size_t)l*CC, x, x, nullptr, nullptr, MROWS, CC, CC);

        ln_kernel<<<MROWS, 256>>>(x, ln2w + l*CC, ln2b + l*CC, lnh, lnl);

        gemm_tn_bf16<true,false,true><<<dim3(C4/128, MROWS/128), thr256>>>(
            lnh, lnl, fcwh + (size_t)l*C4*CC, fcwl + (size_t)l*C4*CC,
            fcb + (size_t)l*C4, nullptr, nullptr, acth, actl, MROWS, C4, CC);

        gemm_tn_bf16<false,true,false><<<dim3(CC/128, MROWS/128), thr256>>>(
            acth, actl, fcpwh + (size_t)l*CC*C4, fcpwl + (size_t)l*CC*C4,
            fcprojb + (size_t)l*CC, x, x, nullptr, nullptr, MROWS, CC, C4);
    }

    ln_kernel<<<MROWS, 256>>>(x, lnfw, lnfb, lnh, lnl);

    gemm_tn_bf16<false,false,false><<<dim3(VP/128, MROWS/128), thr256>>>(
        lnh, lnl, wteh, wtel, nullptr, nullptr, out, nullptr, nullptr, MROWS, VP, CC);
}

// round 6
// speedup vs baseline: 2.9702x; 1.1735x over previous
#include <cuda_runtime.h>
#include <cuda_bf16.h>
#include <math.h>
#include <stdint.h>

// ---------------- problem constants ----------------
#define BATCH 2
#define TT    1024
#define CC    768
#define HH    12
#define DD    64
#define LL    12
#define MROWS (BATCH*TT)      // 2048
#define C3    (3*CC)          // 2304
#define C4    (4*CC)          // 3072
#define VP    50304

// ---------------- scratch (device globals) ----------
__device__ float g_x  [MROWS*CC];
__device__ float g_qkv[MROWS*C3];

__device__ __nv_bfloat16 g_ln_h [MROWS*CC],  g_ln_l [MROWS*CC];
__device__ __nv_bfloat16 g_att_h[MROWS*CC],  g_att_l[MROWS*CC];
__device__ __nv_bfloat16 g_act_h[MROWS*C4],  g_act_l[MROWS*C4];

__device__ __nv_bfloat16 g_qkvw_h [(size_t)LL*C3*CC], g_qkvw_l [(size_t)LL*C3*CC];
__device__ __nv_bfloat16 g_projw_h[(size_t)LL*CC*CC], g_projw_l[(size_t)LL*CC*CC];
__device__ __nv_bfloat16 g_fcw_h  [(size_t)LL*C4*CC], g_fcw_l  [(size_t)LL*C4*CC];
__device__ __nv_bfloat16 g_fcpw_h [(size_t)LL*CC*C4], g_fcpw_l [(size_t)LL*CC*C4];
__device__ __nv_bfloat16 g_wte_h  [(size_t)VP*CC],    g_wte_l  [(size_t)VP*CC];

// ---------------- small helpers ----------------
__device__ __forceinline__ uint32_t pack2(float x, float y, uint32_t &lo)
{
    __nv_bfloat16 xh = __float2bfloat16(x);
    __nv_bfloat16 yh = __float2bfloat16(y);
    __nv_bfloat162 H; H.x = xh; H.y = yh;
    __nv_bfloat162 L; L.x = __float2bfloat16(x - __bfloat162float(xh));
    L.y = __float2bfloat16(y - __bfloat162float(yh));
    lo = *reinterpret_cast<const uint32_t*>(&L);
    return *reinterpret_cast<const uint32_t*>(&H);
}

__device__ __forceinline__ float gelu_tanh(float x) {
    float x3 = x*x*x;
    return 0.5f * x * (1.0f + tanhf(0.7978845608028654f * (x + 0.044715f * x3)));
}

__device__ __forceinline__ uint32_t smem_u32(const void* p) {
    uint32_t a;
    asm("{ .reg .u64 t; cvta.to.shared.u64 t, %1; cvt.u32.u64 %0, t; }"
        : "=r"(a) : "l"(p));
    return a;
}
__device__ __forceinline__ void cpasync16(uint32_t dst, const void* src) {
    asm volatile("cp.async.cg.shared.global [%0], [%1], 16;"
                 :: "r"(dst), "l"(__cvta_generic_to_global(src)));
}
__device__ __forceinline__ void cp_commit() {
    asm volatile("cp.async.commit_group;");
}
template<int N>
__device__ __forceinline__ void cp_wait() {
    asm volatile("cp.async.wait_group %0;" :: "n"(N));
}
__device__ __forceinline__ void ldsm4(uint32_t& r0, uint32_t& r1,
                                      uint32_t& r2, uint32_t& r3, uint32_t addr) {
    asm volatile("ldmatrix.sync.aligned.m8n8.x4.shared.b16 {%0,%1,%2,%3}, [%4];"
                 : "=r"(r0), "=r"(r1), "=r"(r2), "=r"(r3) : "r"(addr));
}
__device__ __forceinline__ void mma16816(float* d,
    uint32_t a0, uint32_t a1, uint32_t a2, uint32_t a3,
    uint32_t b0, uint32_t b1)
{
    asm volatile(
        "mma.sync.aligned.m16n8k16.row.col.f32.bf16.bf16.f32 "
        "{%0,%1,%2,%3}, {%4,%5,%6,%7}, {%8,%9}, {%0,%1,%2,%3};"
        : "+f"(d[0]), "+f"(d[1]), "+f"(d[2]), "+f"(d[3])
        : "r"(a0), "r"(a1), "r"(a2), "r"(a3), "r"(b0), "r"(b1));
}

// ---------------- weight pre-split ----------------
__global__ void split_kernel(const float* __restrict__ s,
                             __nv_bfloat16* __restrict__ h,
                             __nv_bfloat16* __restrict__ l, long n4)
{
    long stride = (long)gridDim.x * blockDim.x;
    for (long i = (long)blockIdx.x * blockDim.x + threadIdx.x; i < n4; i += stride) {
        float4 v = ((const float4*)s)[i];
        uint2 H, L;
        H.x = pack2(v.x, v.y, L.x);
        H.y = pack2(v.z, v.w, L.y);
        ((uint2*)h)[i] = H;
        ((uint2*)l)[i] = L;
    }
}

// ---------------- embedding ----------------
__global__ void embed_kernel(const int* __restrict__ idx,
                             const float* __restrict__ wte,
                             const float* __restrict__ wpe,
                             float* __restrict__ x)
{
    int m = blockIdx.x;
    int t = m & (TT-1);
    int tok = idx[m];
    const float* we = wte + (size_t)tok * CC;
    const float* wp = wpe + (size_t)t * CC;
    float* xr = x + (size_t)m * CC;
    for (int c = threadIdx.x; c < CC; c += blockDim.x)
        xr[c] = we[c] + wp[c];
}

// ---------------- layernorm -> split bf16 ----------------
__global__ void ln_kernel(const float* __restrict__ x,
                          const float* __restrict__ w,
                          const float* __restrict__ b,
                          __nv_bfloat16* __restrict__ yh,
                          __nv_bfloat16* __restrict__ yl)
{
    __shared__ float red[256];
    int row = blockIdx.x;
    int tid = threadIdx.x;
    const float* xr = x + (size_t)row * CC;

    float v0 = xr[tid], v1 = xr[tid+256], v2 = xr[tid+512];
    float local = v0 + v1 + v2;
    red[tid] = local; __syncthreads();
    for (int s = 128; s > 0; s >>= 1) {
        if (tid < s) red[tid] += red[tid+s];
        __syncthreads();
    }
    float mu = red[0] * (1.0f/CC);
    __syncthreads();

    float d0 = v0-mu, d1 = v1-mu, d2 = v2-mu;
    red[tid] = d0*d0 + d1*d1 + d2*d2; __syncthreads();
    for (int s = 128; s > 0; s >>= 1) {
        if (tid < s) red[tid] += red[tid+s];
        __syncthreads();
    }
    float rstd = rsqrtf(red[0] * (1.0f/CC) + 1e-5f);

    size_t base = (size_t)row * CC;
    #pragma unroll
    for (int j = 0; j < 3; j++) {
        int c = tid + j*256;
        float v = (j==0?d0:(j==1?d1:d2))*rstd*w[c] + b[c];
        __nv_bfloat16 hv = __float2bfloat16(v);
        yh[base+c] = hv;
        yl[base+c] = __float2bfloat16(v - __bfloat162float(hv));
    }
}

// ---------------- split-bf16 HMMA GEMM, ldmatrix + cp.async ----------------
// Y = X @ W^T (+bias)(gelu)(+res). X,W pre-split bf16 hi/lo, K-contiguous.
// CTA tile 128x128, BK=32, 8 warps (2x4), warp tile 64x32.
// smem tile: [128 rows][64B], 16B-chunk swizzle c ^= (r>>1)&3 (conflict-free
// for cp.async stores and all ldmatrix phases). Double-buffered, 64KB dynamic.
#define BKG   32
#define TILEB 8192            // one tile: 128*64 bytes
#define STAGEB (4*TILEB)      // AH AL BH BL
#define GSMEM (2*STAGEB)      // 65536

template<bool GELU, bool RES, bool OUTSPLIT>
__global__ void __launch_bounds__(256)
gemm_hmma(const __nv_bfloat16* __restrict__ Xh, const __nv_bfloat16* __restrict__ Xl,
          const __nv_bfloat16* __restrict__ Wh, const __nv_bfloat16* __restrict__ Wl,
          const float* __restrict__ bias, const float* __restrict__ res,
          float* __restrict__ Y,
          __nv_bfloat16* __restrict__ Yh, __nv_bfloat16* __restrict__ Yl,
          int M, int N, int K)
{
    extern __shared__ char sm[];
    const uint32_t sb = smem_u32(sm);

    const int tid  = threadIdx.x;
    const int lane = tid & 31;
    const int warp = tid >> 5;
    const int wm   = warp & 1;
    const int wn   = warp >> 1;
    const int g    = lane >> 2;
    const int tg   = lane & 3;
    const int bm   = blockIdx.x * 128;
    const int bn   = blockIdx.y * 128;

    float d[4][4][4];
    #pragma unroll
    for (int i = 0; i < 4; i++)
        #pragma unroll
        for (int j = 0; j < 4; j++) {
            d[i][j][0]=0.f; d[i][j][1]=0.f; d[i][j][2]=0.f; d[i][j][3]=0.f;
        }

    // ---- global->smem mapping: thread covers row lr, chunks {lcb, lcb+1} ----
    const int lr  = tid >> 1;            // 0..127
    const int lcb = (tid & 1) * 2;       // 0 or 2
    const __nv_bfloat16* xh_p = Xh + (size_t)(bm + lr)*K;
    const __nv_bfloat16* xl_p = Xl + (size_t)(bm + lr)*K;
    const __nv_bfloat16* wh_p = Wh + (size_t)(bn + lr)*K;
    const __nv_bfloat16* wl_p = Wl + (size_t)(bn + lr)*K;
    const int rsw = (lr >> 1) & 3;

    // ---- ldmatrix fragment addresses (constant per thread, per buffer-offset) ----
    uint32_t a_off[4][2], b_off[2][2];
    {
        int arow = wm*64 + (lane & 15);
        int ln16 = lane >> 4;
        #pragma unroll
        for (int fm = 0; fm < 4; fm++) {
            int r = arow + fm*16;
            #pragma unroll
            for (int ks = 0; ks < 2; ks++) {
                int c = ks*2 + ln16;
                a_off[fm][ks] = (uint32_t)(r*64 + ((c ^ ((r>>1)&3)) << 4));
            }
        }
        int q = lane >> 3;
        int brow = wn*32 + ((q >> 1) << 3) + (lane & 7);
        int cadd = q & 1;
        #pragma unroll
        for (int fnp = 0; fnp < 2; fnp++) {
            int r = brow + fnp*16;
            #pragma unroll
            for (int ks = 0; ks < 2; ks++) {
                int c = ks*2 + cadd;
                b_off[fnp][ks] = (uint32_t)(r*64 + ((c ^ ((r>>1)&3)) << 4));
            }
        }
    }

    const int NT = K / BKG;

    // prologue: stage 0
    {
        uint32_t base = sb;
        #pragma unroll
        for (int i = 0; i < 2; i++) {
            int c = lcb + i;
            uint32_t so = (uint32_t)(lr*64 + ((c ^ rsw) << 4));
            cpasync16(base +            so, (const char*)xh_p + c*16);
            cpasync16(base +   TILEB +  so, (const char*)xl_p + c*16);
            cpasync16(base + 2*TILEB +  so, (const char*)wh_p + c*16);
            cpasync16(base + 3*TILEB +  so, (const char*)wl_p + c*16);
        }
        cp_commit();
    }

    for (int t = 0; t < NT; t++) {
        if (t + 1 < NT) {
            const int k0 = (t+1) * BKG;
            uint32_t base = sb + (uint32_t)((t+1) & 1) * STAGEB;
            #pragma unroll
            for (int i = 0; i < 2; i++) {
                int c = lcb + i;
                uint32_t so = (uint32_t)(lr*64 + ((c ^ rsw) << 4));
                cpasync16(base +            so, (const char*)(xh_p + k0) + c*16);
                cpasync16(base +   TILEB +  so, (const char*)(xl_p + k0) + c*16);
                cpasync16(base + 2*TILEB +  so, (const char*)(wh_p + k0) + c*16);
                cpasync16(base + 3*TILEB +  so, (const char*)(wl_p + k0) + c*16);
            }
            cp_commit();
            cp_wait<1>();
        } else {
            cp_wait<0>();
        }
        __syncthreads();

        // ---- compute stage t ----
        {
            uint32_t base = sb + (uint32_t)(t & 1) * STAGEB;
            uint32_t aH = base, aL = base + TILEB;
            uint32_t bH = base + 2*TILEB, bL = base + 3*TILEB;

            #pragma unroll
            for (int ks = 0; ks < 2; ks++) {
                uint32_t ah[4][4], al[4][4], bh[4][2], bl[4][2];
                #pragma unroll
                for (int fm = 0; fm < 4; fm++) {
                    ldsm4(ah[fm][0], ah[fm][1], ah[fm][2], ah[fm][3], aH + a_off[fm][ks]);
                    ldsm4(al[fm][0], al[fm][1], al[fm][2], al[fm][3], aL + a_off[fm][ks]);
                }
                #pragma unroll
                for (int fnp = 0; fnp < 2; fnp++) {
                    uint32_t r0, r1, r2, r3;
                    ldsm4(r0, r1, r2, r3, bH + b_off[fnp][ks]);
                    bh[fnp*2][0]=r0; bh[fnp*2][1]=r1; bh[fnp*2+1][0]=r2; bh[fnp*2+1][1]=r3;
                    ldsm4(r0, r1, r2, r3, bL + b_off[fnp][ks]);
                    bl[fnp*2][0]=r0; bl[fnp*2][1]=r1; bl[fnp*2+1][0]=r2; bl[fnp*2+1][1]=r3;
                }
                #pragma unroll
                for (int fm = 0; fm < 4; fm++)
                    #pragma unroll
                    for (int fn = 0; fn < 4; fn++) {
                        mma16816(d[fm][fn], ah[fm][0],ah[fm][1],ah[fm][2],ah[fm][3],
                                 bh[fn][0], bh[fn][1]);
                        mma16816(d[fm][fn], al[fm][0],al[fm][1],al[fm][2],al[fm][3],
                                 bh[fn][0], bh[fn][1]);
                        mma16816(d[fm][fn], ah[fm][0],ah[fm][1],ah[fm][2],ah[fm][3],
                                 bl[fn][0], bl[fn][1]);
                    }
            }
        }
        __syncthreads();
    }

    // ---- epilogue ----
    #pragma unroll
    for (int fm = 0; fm < 4; fm++) {
        int mrow = bm + wm*64 + fm*16 + g;
        #pragma unroll
        for (int half = 0; half < 2; half++) {
            int m = mrow + half*8;
            #pragma unroll
            for (int fn = 0; fn < 4; fn++) {
                int n0 = bn + wn*32 + fn*8 + tg*2;
                float v0 = d[fm][fn][half*2+0];
                float v1 = d[fm][fn][half*2+1];
                if (bias) { v0 += bias[n0]; v1 += bias[n0+1]; }
                if (GELU) { v0 = gelu_tanh(v0); v1 = gelu_tanh(v1); }
                if (RES) {
                    float2 rv = *(const float2*)&res[(size_t)m*N + n0];
                    v0 += rv.x; v1 += rv.y;
                }
                if (OUTSPLIT) {
                    uint32_t lo;
                    uint32_t hi = pack2(v0, v1, lo);
                    *(uint32_t*)&Yh[(size_t)m*N + n0] = hi;
                    *(uint32_t*)&Yl[(size_t)m*N + n0] = lo;
                } else {
                    float2 o2; o2.x = v0; o2.y = v1;
                    *(float2*)&Y[(size_t)m*N + n0] = o2;
                }
            }
        }
    }
}

// ---------------- flash attention: 64 q/block, 32-key tiles, split-bf16 out ----
#define AQ 64
#define AK 32

__global__ void __launch_bounds__(256)
attn_kernel(const float* __restrict__ qkv,
            __nv_bfloat16* __restrict__ yh, __nv_bfloat16* __restrict__ yl)
{
    __shared__ float Qs[64][68];
    __shared__ float Ks[64][34];
    __shared__ float Vs[AK][68];
    __shared__ float Ps[64][36];

    const int qt  = gridDim.x - 1 - blockIdx.x;
    const int h   = blockIdx.y;
    const int b   = blockIdx.z;
    const int tid = threadIdx.x;
    const int tx  = tid & 15;
    const int ty  = tid >> 4;
    const int q0  = qt * AQ;

    const float* qbase = qkv + (size_t)(b*TT)*C3 + h*DD;
    const float* kbase = qbase + CC;
    const float* vbase = qbase + 2*CC;

    #pragma unroll
    for (int i = 0; i < 4; i++) {
        int v  = tid + i*256;
        int q  = v >> 4;
        int d4 = (v & 15) * 4;
        float4 t = *(const float4*)&qbase[(size_t)(q0+q)*C3 + d4];
        Qs[d4+0][q] = t.x*0.125f; Qs[d4+1][q] = t.y*0.125f;
        Qs[d4+2][q] = t.z*0.125f; Qs[d4+3][q] = t.w*0.125f;
    }

    float o[4][4];
    float m[4], l[4];
    #pragma unroll
    for (int i = 0; i < 4; i++) {
        m[i] = -1e30f; l[i] = 0.0f;
        o[i][0]=0.f; o[i][1]=0.f; o[i][2]=0.f; o[i][3]=0.f;
    }

    const int ntiles = (q0 + AQ) / AK;
    for (int kt = 0; kt < ntiles; kt++) {
        __syncthreads();

        #pragma unroll
        for (int i = 0; i < 2; i++) {
            int v  = tid + i*256;
            int k  = v >> 4;
            int d4 = (v & 15) * 4;
            size_t roff = (size_t)(kt*AK + k)*C3 + d4;
            float4 t = *(const float4*)&kbase[roff];
            Ks[d4+0][k]=t.x; Ks[d4+1][k]=t.y; Ks[d4+2][k]=t.z; Ks[d4+3][k]=t.w;
            float4 u = *(const float4*)&vbase[roff];
            *(float4*)&Vs[k][d4] = u;
        }
        __syncthreads();

        float s[4][2];
        s[0][0]=0.f;s[0][1]=0.f;s[1][0]=0.f;s[1][1]=0.f;
        s[2][0]=0.f;s[2][1]=0.f;s[3][0]=0.f;s[3][1]=0.f;
        #pragma unroll 8
        for (int dd = 0; dd < 64; dd++) {
            float4 a  = *(const float4*)&Qs[dd][ty*4];
            float2 bk = *(const float2*)&Ks[dd][tx*2];
            s[0][0] = fmaf(a.x, bk.x, s[0][0]); s[0][1] = fmaf(a.x, bk.y, s[0][1]);
            s[1][0] = fmaf(a.y, bk.x, s[1][0]); s[1][1] = fmaf(a.y, bk.y, s[1][1]);
            s[2][0] = fmaf(a.z, bk.x, s[2][0]); s[2][1] = fmaf(a.z, bk.y, s[2][1]);
            s[3][0] = fmaf(a.w, bk.x, s[3][0]); s[3][1] = fmaf(a.w, bk.y, s[3][1]);
        }

        const int kg = kt*AK + tx*2;
        #pragma unroll
        for (int i = 0; i < 4; i++) {
            int qg = q0 + ty*4 + i;
            if (kg     > qg) s[i][0] = -1e30f;
            if (kg + 1 > qg) s[i][1] = -1e30f;
        }

        #pragma unroll
        for (int i = 0; i < 4; i++) {
            float smax = fmaxf(s[i][0], s[i][1]);
            smax = fmaxf(smax, __shfl_xor_sync(0xffffffffu, smax, 1));
            smax = fmaxf(smax, __shfl_xor_sync(0xffffffffu, smax, 2));
            smax = fmaxf(smax, __shfl_xor_sync(0xffffffffu, smax, 4));
            smax = fmaxf(smax, __shfl_xor_sync(0xffffffffu, smax, 8));
            float mn    = fmaxf(m[i], smax);
            float alpha = __expf(m[i] - mn);
            float p0 = __expf(s[i][0] - mn);
            float p1 = __expf(s[i][1] - mn);
            float ps = p0 + p1;
            ps += __shfl_xor_sync(0xffffffffu, ps, 1);
            ps += __shfl_xor_sync(0xffffffffu, ps, 2);
            ps += __shfl_xor_sync(0xffffffffu, ps, 4);
            ps += __shfl_xor_sync(0xffffffffu, ps, 8);
            l[i] = l[i]*alpha + ps;
            m[i] = mn;
            o[i][0]*=alpha; o[i][1]*=alpha; o[i][2]*=alpha; o[i][3]*=alpha;
            Ps[ty*4+i][tx*2+0] = p0;
            Ps[ty*4+i][tx*2+1] = p1;
        }
        __syncthreads();

        #pragma unroll 4
        for (int k = 0; k < AK; k++) {
            float4 vv = *(const float4*)&Vs[k][tx*4];
            float a0 = Ps[ty*4+0][k];
            float a1 = Ps[ty*4+1][k];
            float a2 = Ps[ty*4+2][k];
            float a3 = Ps[ty*4+3][k];
            o[0][0]=fmaf(a0,vv.x,o[0][0]); o[0][1]=fmaf(a0,vv.y,o[0][1]); o[0][2]=fmaf(a0,vv.z,o[0][2]); o[0][3]=fmaf(a0,vv.w,o[0][3]);
            o[1][0]=fmaf(a1,vv.x,o[1][0]); o[1][1]=fmaf(a1,vv.y,o[1][1]); o[1][2]=fmaf(a1,vv.z,o[1][2]); o[1][3]=fmaf(a1,vv.w,o[1][3]);
            o[2][0]=fmaf(a2,vv.x,o[2][0]); o[2][1]=fmaf(a2,vv.y,o[2][1]); o[2][2]=fmaf(a2,vv.z,o[2][2]); o[2][3]=fmaf(a2,vv.w,o[2][3]);
            o[3][0]=fmaf(a3,vv.x,o[3][0]); o[3][1]=fmaf(a3,vv.y,o[3][1]); o[3][2]=fmaf(a3,vv.z,o[3][2]); o[3][3]=fmaf(a3,vv.w,o[3][3]);
        }
    }

    #pragma unroll
    for (int i = 0; i < 4; i++) {
        float inv = 1.0f / l[i];
        size_t oidx = (size_t)(b*TT + q0 + ty*4 + i)*CC + h*DD + tx*4;
        uint2 H, L;
        H.x = pack2(o[i][0]*inv, o[i][1]*inv, L.x);
        H.y = pack2(o[i][2]*inv, o[i][3]*inv, L.y);
        *(uint2*)&yh[oidx] = H;
        *(uint2*)&yl[oidx] = L;
    }
}

// ---------------- launch ----------------
extern "C" void kernel_launch(void* const* d_in, const int* in_sizes, int n_in,
                              void* d_out, int out_size)
{
    (void)in_sizes; (void)n_in; (void)out_size;
    const int*   idx     = (const int*)  d_in[0];
    const float* wte     = (const float*)d_in[1];
    const float* wpe     = (const float*)d_in[2];
    const float* ln1w    = (const float*)d_in[3];
    const float* ln1b    = (const float*)d_in[4];
    const float* qkvw    = (const float*)d_in[5];
    const float* qkvb    = (const float*)d_in[6];
    const float* projw   = (const float*)d_in[7];
    const float* projb   = (const float*)d_in[8];
    const float* ln2w    = (const float*)d_in[9];
    const float* ln2b    = (const float*)d_in[10];
    const float* fcw     = (const float*)d_in[11];
    const float* fcb     = (const float*)d_in[12];
    const float* fcprojw = (const float*)d_in[13];
    const float* fcprojb = (const float*)d_in[14];
    const float* lnfw    = (const float*)d_in[15];
    const float* lnfb    = (const float*)d_in[16];
    float* out = (float*)d_out;

    float *x, *qkv;
    __nv_bfloat16 *lnh, *lnl, *atth, *attl, *acth, *actl;
    __nv_bfloat16 *qkvwh, *qkvwl, *projwh, *projwl, *fcwh, *fcwl, *fcpwh, *fcpwl, *wteh, *wtel;
    cudaGetSymbolAddress((void**)&x,    g_x);
    cudaGetSymbolAddress((void**)&qkv,  g_qkv);
    cudaGetSymbolAddress((void**)&lnh,  g_ln_h);   cudaGetSymbolAddress((void**)&lnl,  g_ln_l);
    cudaGetSymbolAddress((void**)&atth, g_att_h);  cudaGetSymbolAddress((void**)&attl, g_att_l);
    cudaGetSymbolAddress((void**)&acth, g_act_h);  cudaGetSymbolAddress((void**)&actl, g_act_l);
    cudaGetSymbolAddress((void**)&qkvwh, g_qkvw_h); cudaGetSymbolAddress((void**)&qkvwl, g_qkvw_l);
    cudaGetSymbolAddress((void**)&projwh,g_projw_h);cudaGetSymbolAddress((void**)&projwl,g_projw_l);
    cudaGetSymbolAddress((void**)&fcwh, g_fcw_h);  cudaGetSymbolAddress((void**)&fcwl, g_fcw_l);
    cudaGetSymbolAddress((void**)&fcpwh,g_fcpw_h); cudaGetSymbolAddress((void**)&fcpwl,g_fcpw_l);
    cudaGetSymbolAddress((void**)&wteh, g_wte_h);  cudaGetSymbolAddress((void**)&wtel, g_wte_l);

    cudaFuncSetAttribute(gemm_hmma<false,false,false>, cudaFuncAttributeMaxDynamicSharedMemorySize, GSMEM);
    cudaFuncSetAttribute(gemm_hmma<false,true ,false>, cudaFuncAttributeMaxDynamicSharedMemorySize, GSMEM);
    cudaFuncSetAttribute(gemm_hmma<true ,false,true >, cudaFuncAttributeMaxDynamicSharedMemorySize, GSMEM);

    const int SB = 1184;
    split_kernel<<<SB, 256>>>(qkvw,    qkvwh,  qkvwl,  (long)LL*C3*CC/4);
    split_kernel<<<SB, 256>>>(projw,   projwh, projwl, (long)LL*CC*CC/4);
    split_kernel<<<SB, 256>>>(fcw,     fcwh,   fcwl,   (long)LL*C4*CC/4);
    split_kernel<<<SB, 256>>>(fcprojw, fcpwh,  fcpwl,  (long)LL*CC*C4/4);
    split_kernel<<<SB, 256>>>(wte,     wteh,   wtel,   (long)VP*CC/4);

    embed_kernel<<<MROWS, 256>>>(idx, wte, wpe, x);

    for (int l = 0; l < LL; l++) {
        ln_kernel<<<MROWS, 256>>>(x, ln1w + l*CC, ln1b + l*CC, lnh, lnl);

        gemm_hmma<false,false,false><<<dim3(MROWS/128, C3/128), 256, GSMEM>>>(
            lnh, lnl, qkvwh + (size_t)l*C3*CC, qkvwl + (size_t)l*C3*CC,
            qkvb + (size_t)l*C3, nullptr, qkv, nullptr, nullptr, MROWS, C3, CC);

        attn_kernel<<<dim3(TT/AQ, HH, BATCH), 256>>>(qkv, atth, attl);

        gemm_hmma<false,true,false><<<dim3(MROWS/128, CC/128), 256, GSMEM>>>(
            atth, attl, projwh + (size_t)l*CC*CC, projwl + (size_t)l*CC*CC,
            projb + (size_t)l*CC, x, x, nullptr, nullptr, MROWS, CC, CC);

        ln_kernel<<<MROWS, 256>>>(x, ln2w + l*CC, ln2b + l*CC, lnh, lnl);

        gemm_hmma<true,false,true><<<dim3(MROWS/128, C4/128), 256, GSMEM>>>(
            lnh, lnl, fcwh + (size_t)l*C4*CC, fcwl + (size_t)l*C4*CC,
            fcb + (size_t)l*C4, nullptr, nullptr, acth, actl, MROWS, C4, CC);

        gemm_hmma<false,true,false><<<dim3(MROWS/128, CC/128), 256, GSMEM>>>(
            acth, actl, fcpwh + (size_t)l*CC*C4, fcpwl + (size_t)l*CC*C4,
            fcprojb + (size_t)l*CC, x, x, nullptr, nullptr, MROWS, CC, C4);
    }

    ln_kernel<<<MROWS, 256>>>(x, lnfw, lnfb, lnh, lnl);

    gemm_hmma<false,false,false><<<dim3(MROWS/128, VP/128), 256, GSMEM>>>(
        lnh, lnl, wteh, wtel, nullptr, nullptr, out, nullptr, nullptr, MROWS, VP, CC);
}

// round 7
// speedup vs baseline: 3.0747x; 1.0352x over previous
#include <cuda_runtime.h>
#include <cuda_bf16.h>
#include <math.h>
#include <stdint.h>

// ---------------- problem constants ----------------
#define BATCH 2
#define TT    1024
#define CC    768
#define HH    12
#define DD    64
#define LL    12
#define MROWS (BATCH*TT)      // 2048
#define C3    (3*CC)          // 2304
#define C4    (4*CC)          // 3072
#define VP    50304

// ---------------- scratch (device globals) ----------
__device__ float g_x  [MROWS*CC];
__device__ float g_qkv[MROWS*C3];

__device__ __nv_bfloat16 g_ln_h [MROWS*CC],  g_ln_l [MROWS*CC];
__device__ __nv_bfloat16 g_att_h[MROWS*CC],  g_att_l[MROWS*CC];
__device__ __nv_bfloat16 g_act_h[MROWS*C4],  g_act_l[MROWS*C4];

__device__ __nv_bfloat16 g_qkvw_h [(size_t)LL*C3*CC], g_qkvw_l [(size_t)LL*C3*CC];
__device__ __nv_bfloat16 g_projw_h[(size_t)LL*CC*CC], g_projw_l[(size_t)LL*CC*CC];
__device__ __nv_bfloat16 g_fcw_h  [(size_t)LL*C4*CC], g_fcw_l  [(size_t)LL*C4*CC];
__device__ __nv_bfloat16 g_fcpw_h [(size_t)LL*CC*C4], g_fcpw_l [(size_t)LL*CC*C4];
__device__ __nv_bfloat16 g_wte_h  [(size_t)VP*CC],    g_wte_l  [(size_t)VP*CC];

// ---------------- small helpers ----------------
__device__ __forceinline__ uint32_t pack2(float x, float y, uint32_t &lo)
{
    __nv_bfloat16 xh = __float2bfloat16(x);
    __nv_bfloat16 yh = __float2bfloat16(y);
    __nv_bfloat162 H; H.x = xh; H.y = yh;
    __nv_bfloat162 L; L.x = __float2bfloat16(x - __bfloat162float(xh));
    L.y = __float2bfloat16(y - __bfloat162float(yh));
    lo = *reinterpret_cast<const uint32_t*>(&L);
    return *reinterpret_cast<const uint32_t*>(&H);
}

__device__ __forceinline__ float gelu_tanh(float x) {
    float x3 = x*x*x;
    return 0.5f * x * (1.0f + tanhf(0.7978845608028654f * (x + 0.044715f * x3)));
}

__device__ __forceinline__ uint32_t smem_u32(const void* p) {
    uint32_t a;
    asm("{ .reg .u64 t; cvta.to.shared.u64 t, %1; cvt.u32.u64 %0, t; }"
        : "=r"(a) : "l"(p));
    return a;
}
__device__ __forceinline__ void cpasync16(uint32_t dst, const void* src) {
    asm volatile("cp.async.cg.shared.global [%0], [%1], 16;"
                 :: "r"(dst), "l"(__cvta_generic_to_global(src)));
}
__device__ __forceinline__ void cp_commit() {
    asm volatile("cp.async.commit_group;");
}
template<int N>
__device__ __forceinline__ void cp_wait() {
    asm volatile("cp.async.wait_group %0;" :: "n"(N));
}
__device__ __forceinline__ void ldsm4(uint32_t& r0, uint32_t& r1,
                                      uint32_t& r2, uint32_t& r3, uint32_t addr) {
    asm volatile("ldmatrix.sync.aligned.m8n8.x4.shared.b16 {%0,%1,%2,%3}, [%4];"
                 : "=r"(r0), "=r"(r1), "=r"(r2), "=r"(r3) : "r"(addr));
}
__device__ __forceinline__ void mma16816(float* d,
    uint32_t a0, uint32_t a1, uint32_t a2, uint32_t a3,
    uint32_t b0, uint32_t b1)
{
    asm volatile(
        "mma.sync.aligned.m16n8k16.row.col.f32.bf16.bf16.f32 "
        "{%0,%1,%2,%3}, {%4,%5,%6,%7}, {%8,%9}, {%0,%1,%2,%3};"
        : "+f"(d[0]), "+f"(d[1]), "+f"(d[2]), "+f"(d[3])
        : "r"(a0), "r"(a1), "r"(a2), "r"(a3), "r"(b0), "r"(b1));
}

// ---------------- weight pre-split ----------------
__global__ void split_kernel(const float* __restrict__ s,
                             __nv_bfloat16* __restrict__ h,
                             __nv_bfloat16* __restrict__ l, long n4)
{
    long stride = (long)gridDim.x * blockDim.x;
    for (long i = (long)blockIdx.x * blockDim.x + threadIdx.x; i < n4; i += stride) {
        float4 v = ((const float4*)s)[i];
        uint2 H, L;
        H.x = pack2(v.x, v.y, L.x);
        H.y = pack2(v.z, v.w, L.y);
        ((uint2*)h)[i] = H;
        ((uint2*)l)[i] = L;
    }
}

// ---------------- embedding ----------------
__global__ void embed_kernel(const int* __restrict__ idx,
                             const float* __restrict__ wte,
                             const float* __restrict__ wpe,
                             float* __restrict__ x)
{
    int m = blockIdx.x;
    int t = m & (TT-1);
    int tok = idx[m];
    const float* we = wte + (size_t)tok * CC;
    const float* wp = wpe + (size_t)t * CC;
    float* xr = x + (size_t)m * CC;
    for (int c = threadIdx.x; c < CC; c += blockDim.x)
        xr[c] = we[c] + wp[c];
}

// ---------------- layernorm (warp-shuffle reductions, 2 barriers) ----------
__global__ void ln_kernel(const float* __restrict__ x,
                          const float* __restrict__ w,
                          const float* __restrict__ b,
                          __nv_bfloat16* __restrict__ yh,
                          __nv_bfloat16* __restrict__ yl)
{
    __shared__ float red[16];
    int row  = blockIdx.x;
    int tid  = threadIdx.x;
    int lane = tid & 31;
    int warp = tid >> 5;
    const float* xr = x + (size_t)row * CC;

    float v0 = xr[tid], v1 = xr[tid+256], v2 = xr[tid+512];
    float s = v0 + v1 + v2;
    #pragma unroll
    for (int o = 16; o; o >>= 1) s += __shfl_xor_sync(0xffffffffu, s, o);
    if (!lane) red[warp] = s;
    __syncthreads();
    float mu = (red[0]+red[1]+red[2]+red[3]+red[4]+red[5]+red[6]+red[7]) * (1.0f/CC);

    float d0 = v0-mu, d1 = v1-mu, d2 = v2-mu;
    float q = d0*d0 + d1*d1 + d2*d2;
    #pragma unroll
    for (int o = 16; o; o >>= 1) q += __shfl_xor_sync(0xffffffffu, q, o);
    if (!lane) red[8+warp] = q;
    __syncthreads();
    float rstd = rsqrtf((red[8]+red[9]+red[10]+red[11]+red[12]+red[13]+red[14]+red[15])
                        * (1.0f/CC) + 1e-5f);

    size_t base = (size_t)row * CC;
    #pragma unroll
    for (int j = 0; j < 3; j++) {
        int c = tid + j*256;
        float v = (j==0?d0:(j==1?d1:d2))*rstd*w[c] + b[c];
        __nv_bfloat16 hv = __float2bfloat16(v);
        yh[base+c] = hv;
        yl[base+c] = __float2bfloat16(v - __bfloat162float(hv));
    }
}

// ---------------- split-bf16 HMMA GEMM, ldmatrix + 3-stage cp.async ----------
// Y = X @ W^T (+bias)(gelu)(+res). X,W pre-split bf16 hi/lo, K-contiguous.
// CTA tile 128x128, BK=32, 8 warps (2x4), warp tile 64x32.
// smem tile: [128 rows][64B], 16B-chunk swizzle c ^= (r>>1)&3. 3 stages = 96KB.
#define BKG   32
#define TILEB 8192            // one tile: 128*64 bytes
#define STAGEB (4*TILEB)      // AH AL BH BL = 32KB
#define GSMEM (3*STAGEB)      // 98304

template<bool GELU, bool RES, bool OUTSPLIT>
__global__ void __launch_bounds__(256)
gemm_hmma(const __nv_bfloat16* __restrict__ Xh, const __nv_bfloat16* __restrict__ Xl,
          const __nv_bfloat16* __restrict__ Wh, const __nv_bfloat16* __restrict__ Wl,
          const float* __restrict__ bias, const float* __restrict__ res,
          float* __restrict__ Y,
          __nv_bfloat16* __restrict__ Yh, __nv_bfloat16* __restrict__ Yl,
          int M, int N, int K)
{
    extern __shared__ char sm[];
    const uint32_t sb = smem_u32(sm);

    const int tid  = threadIdx.x;
    const int lane = tid & 31;
    const int warp = tid >> 5;
    const int wm   = warp & 1;
    const int wn   = warp >> 1;
    const int g    = lane >> 2;
    const int tg   = lane & 3;
    const int bm   = blockIdx.x * 128;
    const int bn   = blockIdx.y * 128;

    float d[4][4][4];
    #pragma unroll
    for (int i = 0; i < 4; i++)
        #pragma unroll
        for (int j = 0; j < 4; j++) {
            d[i][j][0]=0.f; d[i][j][1]=0.f; d[i][j][2]=0.f; d[i][j][3]=0.f;
        }

    // ---- global->smem mapping: thread covers row lr, chunks {lcb, lcb+1} ----
    const int lr  = tid >> 1;
    const int lcb = (tid & 1) * 2;
    const __nv_bfloat16* xh_p = Xh + (size_t)(bm + lr)*K;
    const __nv_bfloat16* xl_p = Xl + (size_t)(bm + lr)*K;
    const __nv_bfloat16* wh_p = Wh + (size_t)(bn + lr)*K;
    const __nv_bfloat16* wl_p = Wl + (size_t)(bn + lr)*K;
    const int rsw = (lr >> 1) & 3;
    uint32_t so[2];
    #pragma unroll
    for (int i = 0; i < 2; i++)
        so[i] = (uint32_t)(lr*64 + (((lcb+i) ^ rsw) << 4));

    // ---- ldmatrix fragment addresses ----
    uint32_t a_off[4][2], b_off[2][2];
    {
        int arow = wm*64 + (lane & 15);
        int ln16 = lane >> 4;
        #pragma unroll
        for (int fm = 0; fm < 4; fm++) {
            int r = arow + fm*16;
            #pragma unroll
            for (int ks = 0; ks < 2; ks++) {
                int c = ks*2 + ln16;
                a_off[fm][ks] = (uint32_t)(r*64 + ((c ^ ((r>>1)&3)) << 4));
            }
        }
        int q = lane >> 3;
        int brow = wn*32 + ((q >> 1) << 3) + (lane & 7);
        int cadd = q & 1;
        #pragma unroll
        for (int fnp = 0; fnp < 2; fnp++) {
            int r = brow + fnp*16;
            #pragma unroll
            for (int ks = 0; ks < 2; ks++) {
                int c = ks*2 + cadd;
                b_off[fnp][ks] = (uint32_t)(r*64 + ((c ^ ((r>>1)&3)) << 4));
            }
        }
    }

    const int NT = K / BKG;

    // prologue: stages 0 and 1 (NT >= 2 always here)
    #pragma unroll
    for (int s = 0; s < 2; s++) {
        uint32_t base = sb + (uint32_t)s * STAGEB;
        const int k0 = s * BKG;
        #pragma unroll
        for (int i = 0; i < 2; i++) {
            int c = lcb + i;
            cpasync16(base +            so[i], (const char*)(xh_p + k0) + c*16);
            cpasync16(base +   TILEB +  so[i], (const char*)(xl_p + k0) + c*16);
            cpasync16(base + 2*TILEB +  so[i], (const char*)(wh_p + k0) + c*16);
            cpasync16(base + 3*TILEB +  so[i], (const char*)(wl_p + k0) + c*16);
        }
        cp_commit();
    }

    int bufc = 0;   // compute buffer for stage t
    for (int t = 0; t < NT; t++) {
        cp_wait<1>();          // stage t data arrived (for this thread)
        __syncthreads();       // all threads' data visible; all done computing t-1

        // issue stage t+2 into buffer (bufc+2)%3 (holds stage t-1, now free)
        if (t + 2 < NT) {
            int bufs = bufc + 2; if (bufs >= 3) bufs -= 3;
            uint32_t base = sb + (uint32_t)bufs * STAGEB;
            const int k0 = (t+2) * BKG;
            #pragma unroll
            for (int i = 0; i < 2; i++) {
                int c = lcb + i;
                cpasync16(base +            so[i], (const char*)(xh_p + k0) + c*16);
                cpasync16(base +   TILEB +  so[i], (const char*)(xl_p + k0) + c*16);
                cpasync16(base + 2*TILEB +  so[i], (const char*)(wh_p + k0) + c*16);
                cpasync16(base + 3*TILEB +  so[i], (const char*)(wl_p + k0) + c*16);
            }
        }
        cp_commit();           // one group per iteration (possibly empty)

        // ---- compute stage t ----
        {
            uint32_t base = sb + (uint32_t)bufc * STAGEB;
            uint32_t aH = base, aL = base + TILEB;
            uint32_t bH = base + 2*TILEB, bL = base + 3*TILEB;

            #pragma unroll
            for (int ks = 0; ks < 2; ks++) {
                uint32_t ah[4][4], al[4][4], bh[4][2], bl[4][2];
                #pragma unroll
                for (int fm = 0; fm < 4; fm++) {
                    ldsm4(ah[fm][0], ah[fm][1], ah[fm][2], ah[fm][3], aH + a_off[fm][ks]);
                    ldsm4(al[fm][0], al[fm][1], al[fm][2], al[fm][3], aL + a_off[fm][ks]);
                }
                #pragma unroll
                for (int fnp = 0; fnp < 2; fnp++) {
                    uint32_t r0, r1, r2, r3;
                    ldsm4(r0, r1, r2, r3, bH + b_off[fnp][ks]);
                    bh[fnp*2][0]=r0; bh[fnp*2][1]=r1; bh[fnp*2+1][0]=r2; bh[fnp*2+1][1]=r3;
                    ldsm4(r0, r1, r2, r3, bL + b_off[fnp][ks]);
                    bl[fnp*2][0]=r0; bl[fnp*2][1]=r1; bl[fnp*2+1][0]=r2; bl[fnp*2+1][1]=r3;
                }
                #pragma unroll
                for (int fm = 0; fm < 4; fm++)
                    #pragma unroll
                    for (int fn = 0; fn < 4; fn++) {
                        mma16816(d[fm][fn], ah[fm][0],ah[fm][1],ah[fm][2],ah[fm][3],
                                 bh[fn][0], bh[fn][1]);
                        mma16816(d[fm][fn], al[fm][0],al[fm][1],al[fm][2],al[fm][3],
                                 bh[fn][0], bh[fn][1]);
                        mma16816(d[fm][fn], ah[fm][0],ah[fm][1],ah[fm][2],ah[fm][3],
                                 bl[fn][0], bl[fn][1]);
                    }
            }
        }
        bufc = (bufc + 1 == 3) ? 0 : bufc + 1;
    }

    // ---- epilogue ----
    #pragma unroll
    for (int fm = 0; fm < 4; fm++) {
        int mrow = bm + wm*64 + fm*16 + g;
        #pragma unroll
        for (int half = 0; half < 2; half++) {
            int m = mrow + half*8;
            #pragma unroll
            for (int fn = 0; fn < 4; fn++) {
                int n0 = bn + wn*32 + fn*8 + tg*2;
                float v0 = d[fm][fn][half*2+0];
                float v1 = d[fm][fn][half*2+1];
                if (bias) { v0 += bias[n0]; v1 += bias[n0+1]; }
                if (GELU) { v0 = gelu_tanh(v0); v1 = gelu_tanh(v1); }
                if (RES) {
                    float2 rv = *(const float2*)&res[(size_t)m*N + n0];
                    v0 += rv.x; v1 += rv.y;
                }
                if (OUTSPLIT) {
                    uint32_t lo;
                    uint32_t hi = pack2(v0, v1, lo);
                    *(uint32_t*)&Yh[(size_t)m*N + n0] = hi;
                    *(uint32_t*)&Yl[(size_t)m*N + n0] = lo;
                } else {
                    float2 o2; o2.x = v0; o2.y = v1;
                    *(float2*)&Y[(size_t)m*N + n0] = o2;
                }
            }
        }
    }
}

// ---------------- flash attention: 64 q/block, 32-key tiles, split-bf16 out ----
#define AQ 64
#define AK 32

__global__ void __launch_bounds__(256)
attn_kernel(const float* __restrict__ qkv,
            __nv_bfloat16* __restrict__ yh, __nv_bfloat16* __restrict__ yl)
{
    __shared__ float Qs[64][68];
    __shared__ float Ks[64][34];
    __shared__ float Vs[AK][68];
    __shared__ float Ps[64][36];

    const int qt  = gridDim.x - 1 - blockIdx.x;
    const int h   = blockIdx.y;
    const int b   = blockIdx.z;
    const int tid = threadIdx.x;
    const int tx  = tid & 15;
    const int ty  = tid >> 4;
    const int q0  = qt * AQ;

    const float* qbase = qkv + (size_t)(b*TT)*C3 + h*DD;
    const float* kbase = qbase + CC;
    const float* vbase = qbase + 2*CC;

    #pragma unroll
    for (int i = 0; i < 4; i++) {
        int v  = tid + i*256;
        int q  = v >> 4;
        int d4 = (v & 15) * 4;
        float4 t = *(const float4*)&qbase[(size_t)(q0+q)*C3 + d4];
        Qs[d4+0][q] = t.x*0.125f; Qs[d4+1][q] = t.y*0.125f;
        Qs[d4+2][q] = t.z*0.125f; Qs[d4+3][q] = t.w*0.125f;
    }

    float o[4][4];
    float m[4], l[4];
    #pragma unroll
    for (int i = 0; i < 4; i++) {
        m[i] = -1e30f; l[i] = 0.0f;
        o[i][0]=0.f; o[i][1]=0.f; o[i][2]=0.f; o[i][3]=0.f;
    }

    const int ntiles = (q0 + AQ) / AK;
    for (int kt = 0; kt < ntiles; kt++) {
        __syncthreads();

        #pragma unroll
        for (int i = 0; i < 2; i++) {
            int v  = tid + i*256;
            int k  = v >> 4;
            int d4 = (v & 15) * 4;
            size_t roff = (size_t)(kt*AK + k)*C3 + d4;
            float4 t = *(const float4*)&kbase[roff];
            Ks[d4+0][k]=t.x; Ks[d4+1][k]=t.y; Ks[d4+2][k]=t.z; Ks[d4+3][k]=t.w;
            float4 u = *(const float4*)&vbase[roff];
            *(float4*)&Vs[k][d4] = u;
        }
        __syncthreads();

        float s[4][2];
        s[0][0]=0.f;s[0][1]=0.f;s[1][0]=0.f;s[1][1]=0.f;
        s[2][0]=0.f;s[2][1]=0.f;s[3][0]=0.f;s[3][1]=0.f;
        #pragma unroll 8
        for (int dd = 0; dd < 64; dd++) {
            float4 a  = *(const float4*)&Qs[dd][ty*4];
            float2 bk = *(const float2*)&Ks[dd][tx*2];
            s[0][0] = fmaf(a.x, bk.x, s[0][0]); s[0][1] = fmaf(a.x, bk.y, s[0][1]);
            s[1][0] = fmaf(a.y, bk.x, s[1][0]); s[1][1] = fmaf(a.y, bk.y, s[1][1]);
            s[2][0] = fmaf(a.z, bk.x, s[2][0]); s[2][1] = fmaf(a.z, bk.y, s[2][1]);
            s[3][0] = fmaf(a.w, bk.x, s[3][0]); s[3][1] = fmaf(a.w, bk.y, s[3][1]);
        }

        const int kg = kt*AK + tx*2;
        #pragma unroll
        for (int i = 0; i < 4; i++) {
            int qg = q0 + ty*4 + i;
            if (kg     > qg) s[i][0] = -1e30f;
            if (kg + 1 > qg) s[i][1] = -1e30f;
        }

        #pragma unroll
        for (int i = 0; i < 4; i++) {
            float smax = fmaxf(s[i][0], s[i][1]);
            smax = fmaxf(smax, __shfl_xor_sync(0xffffffffu, smax, 1));
            smax = fmaxf(smax, __shfl_xor_sync(0xffffffffu, smax, 2));
            smax = fmaxf(smax, __shfl_xor_sync(0xffffffffu, smax, 4));
            smax = fmaxf(smax, __shfl_xor_sync(0xffffffffu, smax, 8));
            float mn    = fmaxf(m[i], smax);
            float alpha = __expf(m[i] - mn);
            float p0 = __expf(s[i][0] - mn);
            float p1 = __expf(s[i][1] - mn);
            float ps = p0 + p1;
            ps += __shfl_xor_sync(0xffffffffu, ps, 1);
            ps += __shfl_xor_sync(0xffffffffu, ps, 2);
            ps += __shfl_xor_sync(0xffffffffu, ps, 4);
            ps += __shfl_xor_sync(0xffffffffu, ps, 8);
            l[i] = l[i]*alpha + ps;
            m[i] = mn;
            o[i][0]*=alpha; o[i][1]*=alpha; o[i][2]*=alpha; o[i][3]*=alpha;
            Ps[ty*4+i][tx*2+0] = p0;
            Ps[ty*4+i][tx*2+1] = p1;
        }
        __syncthreads();

        #pragma unroll 4
        for (int k = 0; k < AK; k++) {
            float4 vv = *(const float4*)&Vs[k][tx*4];
            float a0 = Ps[ty*4+0][k];
            float a1 = Ps[ty*4+1][k];
            float a2 = Ps[ty*4+2][k];
            float a3 = Ps[ty*4+3][k];
            o[0][0]=fmaf(a0,vv.x,o[0][0]); o[0][1]=fmaf(a0,vv.y,o[0][1]); o[0][2]=fmaf(a0,vv.z,o[0][2]); o[0][3]=fmaf(a0,vv.w,o[0][3]);
            o[1][0]=fmaf(a1,vv.x,o[1][0]); o[1][1]=fmaf(a1,vv.y,o[1][1]); o[1][2]=fmaf(a1,vv.z,o[1][2]); o[1][3]=fmaf(a1,vv.w,o[1][3]);
            o[2][0]=fmaf(a2,vv.x,o[2][0]); o[2][1]=fmaf(a2,vv.y,o[2][1]); o[2][2]=fmaf(a2,vv.z,o[2][2]); o[2][3]=fmaf(a2,vv.w,o[2][3]);
            o[3][0]=fmaf(a3,vv.x,o[3][0]); o[3][1]=fmaf(a3,vv.y,o[3][1]); o[3][2]=fmaf(a3,vv.z,o[3][2]); o[3][3]=fmaf(a3,vv.w,o[3][3]);
        }
    }

    #pragma unroll
    for (int i = 0; i < 4; i++) {
        float inv = 1.0f / l[i];
        size_t oidx = (size_t)(b*TT + q0 + ty*4 + i)*CC + h*DD + tx*4;
        uint2 H, L;
        H.x = pack2(o[i][0]*inv, o[i][1]*inv, L.x);
        H.y = pack2(o[i][2]*inv, o[i][3]*inv, L.y);
        *(uint2*)&yh[oidx] = H;
        *(uint2*)&yl[oidx] = L;
    }
}

// ---------------- launch ----------------
extern "C" void kernel_launch(void* const* d_in, const int* in_sizes, int n_in,
                              void* d_out, int out_size)
{
    (void)in_sizes; (void)n_in; (void)out_size;
    const int*   idx     = (const int*)  d_in[0];
    const float* wte     = (const float*)d_in[1];
    const float* wpe     = (const float*)d_in[2];
    const float* ln1w    = (const float*)d_in[3];
    const float* ln1b    = (const float*)d_in[4];
    const float* qkvw    = (const float*)d_in[5];
    const float* qkvb    = (const float*)d_in[6];
    const float* projw   = (const float*)d_in[7];
    const float* projb   = (const float*)d_in[8];
    const float* ln2w    = (const float*)d_in[9];
    const float* ln2b    = (const float*)d_in[10];
    const float* fcw     = (const float*)d_in[11];
    const float* fcb     = (const float*)d_in[12];
    const float* fcprojw = (const float*)d_in[13];
    const float* fcprojb = (const float*)d_in[14];
    const float* lnfw    = (const float*)d_in[15];
    const float* lnfb    = (const float*)d_in[16];
    float* out = (float*)d_out;

    float *x, *qkv;
    __nv_bfloat16 *lnh, *lnl, *atth, *attl, *acth, *actl;
    __nv_bfloat16 *qkvwh, *qkvwl, *projwh, *projwl, *fcwh, *fcwl, *fcpwh, *fcpwl, *wteh, *wtel;
    cudaGetSymbolAddress((void**)&x,    g_x);
    cudaGetSymbolAddress((void**)&qkv,  g_qkv);
    cudaGetSymbolAddress((void**)&lnh,  g_ln_h);   cudaGetSymbolAddress((void**)&lnl,  g_ln_l);
    cudaGetSymbolAddress((void**)&atth, g_att_h);  cudaGetSymbolAddress((void**)&attl, g_att_l);
    cudaGetSymbolAddress((void**)&acth, g_act_h);  cudaGetSymbolAddress((void**)&actl, g_act_l);
    cudaGetSymbolAddress((void**)&qkvwh, g_qkvw_h); cudaGetSymbolAddress((void**)&qkvwl, g_qkvw_l);
    cudaGetSymbolAddress((void**)&projwh,g_projw_h);cudaGetSymbolAddress((void**)&projwl,g_projw_l);
    cudaGetSymbolAddress((void**)&fcwh, g_fcw_h);  cudaGetSymbolAddress((void**)&fcwl, g_fcw_l);
    cudaGetSymbolAddress((void**)&fcpwh,g_fcpw_h); cudaGetSymbolAddress((void**)&fcpwl,g_fcpw_l);
    cudaGetSymbolAddress((void**)&wteh, g_wte_h);  cudaGetSymbolAddress((void**)&wtel, g_wte_l);

    cudaFuncSetAttribute(gemm_hmma<false,false,false>, cudaFuncAttributeMaxDynamicSharedMemorySize, GSMEM);
    cudaFuncSetAttribute(gemm_hmma<false,true ,false>, cudaFuncAttributeMaxDynamicSharedMemorySize, GSMEM);
    cudaFuncSetAttribute(gemm_hmma<true ,false,true >, cudaFuncAttributeMaxDynamicSharedMemorySize, GSMEM);

    const int SB = 1184;
    split_kernel<<<SB, 256>>>(qkvw,    qkvwh,  qkvwl,  (long)LL*C3*CC/4);
    split_kernel<<<SB, 256>>>(projw,   projwh, projwl, (long)LL*CC*CC/4);
    split_kernel<<<SB, 256>>>(fcw,     fcwh,   fcwl,   (long)LL*C4*CC/4);
    split_kernel<<<SB, 256>>>(fcprojw, fcpwh,  fcpwl,  (long)LL*CC*C4/4);
    split_kernel<<<SB, 256>>>(wte,     wteh,   wtel,   (long)VP*CC/4);

    embed_kernel<<<MROWS, 256>>>(idx, wte, wpe, x);

    for (int l = 0; l < LL; l++) {
        ln_kernel<<<MROWS, 256>>>(x, ln1w + l*CC, ln1b + l*CC, lnh, lnl);

        gemm_hmma<false,false,false><<<dim3(MROWS/128, C3/128), 256, GSMEM>>>(
            lnh, lnl, qkvwh + (size_t)l*C3*CC, qkvwl + (size_t)l*C3*CC,
            qkvb + (size_t)l*C3, nullptr, qkv, nullptr, nullptr, MROWS, C3, CC);

        attn_kernel<<<dim3(TT/AQ, HH, BATCH), 256>>>(qkv, atth, attl);

        gemm_hmma<false,true,false><<<dim3(MROWS/128, CC/128), 256, GSMEM>>>(
            atth, attl, projwh + (size_t)l*CC*CC, projwl + (size_t)l*CC*CC,
            projb + (size_t)l*CC, x, x, nullptr, nullptr, MROWS, CC, CC);

        ln_kernel<<<MROWS, 256>>>(x, ln2w + l*CC, ln2b + l*CC, lnh, lnl);

        gemm_hmma<true,false,true><<<dim3(MROWS/128, C4/128), 256, GSMEM>>>(
            lnh, lnl, fcwh + (size_t)l*C4*CC, fcwl + (size_t)l*C4*CC,
            fcb + (size_t)l*C4, nullptr, nullptr, acth, actl, MROWS, C4, CC);

        gemm_hmma<false,true,false><<<dim3(MROWS/128, CC/128), 256, GSMEM>>>(
            acth, actl, fcpwh + (size_t)l*CC*C4, fcpwl + (size_t)l*CC*C4,
            fcprojb + (size_t)l*CC, x, x, nullptr, nullptr, MROWS, CC, C4);
    }

    ln_kernel<<<MROWS, 256>>>(x, lnfw, lnfb, lnh, lnl);

    gemm_hmma<false,false,false><<<dim3(MROWS/128, VP/128), 256, GSMEM>>>(
        lnh, lnl, wteh, wtel, nullptr, nullptr, out, nullptr, nullptr, MROWS, VP, CC);
}

// round 8
// speedup vs baseline: 3.6264x; 1.1794x over previous
#include <cuda_runtime.h>
#include <cuda_bf16.h>
#include <math.h>
#include <stdint.h>

// ---------------- problem constants ----------------
#define BATCH 2
#define TT    1024
#define CC    768
#define HH    12
#define DD    64
#define LL    12
#define MROWS (BATCH*TT)      // 2048
#define C3    (3*CC)          // 2304
#define C4    (4*CC)          // 3072
#define VP    50304

// ---------------- scratch (device globals) ----------
__device__ float g_x  [MROWS*CC];
__device__ float g_qkv[MROWS*C3];

__device__ __nv_bfloat16 g_ln_h [MROWS*CC],  g_ln_l [MROWS*CC];
__device__ __nv_bfloat16 g_att_h[MROWS*CC],  g_att_l[MROWS*CC];
__device__ __nv_bfloat16 g_act_h[MROWS*C4],  g_act_l[MROWS*C4];

__device__ __nv_bfloat16 g_qkvw_h [(size_t)LL*C3*CC], g_qkvw_l [(size_t)LL*C3*CC];
__device__ __nv_bfloat16 g_projw_h[(size_t)LL*CC*CC], g_projw_l[(size_t)LL*CC*CC];
__device__ __nv_bfloat16 g_fcw_h  [(size_t)LL*C4*CC], g_fcw_l  [(size_t)LL*C4*CC];
__device__ __nv_bfloat16 g_fcpw_h [(size_t)LL*CC*C4], g_fcpw_l [(size_t)LL*CC*C4];
__device__ __nv_bfloat16 g_wte_h  [(size_t)VP*CC],    g_wte_l  [(size_t)VP*CC];

// ---------------- small helpers ----------------
__device__ __forceinline__ uint32_t pack2(float x, float y, uint32_t &lo)
{
    __nv_bfloat16 xh = __float2bfloat16(x);
    __nv_bfloat16 yh = __float2bfloat16(y);
    __nv_bfloat162 H; H.x = xh; H.y = yh;
    __nv_bfloat162 L; L.x = __float2bfloat16(x - __bfloat162float(xh));
    L.y = __float2bfloat16(y - __bfloat162float(yh));
    lo = *reinterpret_cast<const uint32_t*>(&L);
    return *reinterpret_cast<const uint32_t*>(&H);
}

__device__ __forceinline__ float gelu_tanh(float x) {
    float x3 = x*x*x;
    return 0.5f * x * (1.0f + tanhf(0.7978845608028654f * (x + 0.044715f * x3)));
}

__device__ __forceinline__ float ex2f(float x) {
    float y;
    asm("ex2.approx.f32 %0, %1;" : "=f"(y) : "f"(x));
    return y;
}

__device__ __forceinline__ uint32_t smem_u32(const void* p) {
    uint32_t a;
    asm("{ .reg .u64 t; cvta.to.shared.u64 t, %1; cvt.u32.u64 %0, t; }"
        : "=r"(a) : "l"(p));
    return a;
}
__device__ __forceinline__ void cpasync16(uint32_t dst, const void* src) {
    asm volatile("cp.async.cg.shared.global [%0], [%1], 16;"
                 :: "r"(dst), "l"(__cvta_generic_to_global(src)));
}
__device__ __forceinline__ void cp_commit() {
    asm volatile("cp.async.commit_group;");
}
template<int N>
__device__ __forceinline__ void cp_wait() {
    asm volatile("cp.async.wait_group %0;" :: "n"(N));
}
__device__ __forceinline__ void ldsm4(uint32_t& r0, uint32_t& r1,
                                      uint32_t& r2, uint32_t& r3, uint32_t addr) {
    asm volatile("ldmatrix.sync.aligned.m8n8.x4.shared.b16 {%0,%1,%2,%3}, [%4];"
                 : "=r"(r0), "=r"(r1), "=r"(r2), "=r"(r3) : "r"(addr));
}
__device__ __forceinline__ void ldsm4t(uint32_t& r0, uint32_t& r1,
                                       uint32_t& r2, uint32_t& r3, uint32_t addr) {
    asm volatile("ldmatrix.sync.aligned.m8n8.x4.trans.shared.b16 {%0,%1,%2,%3}, [%4];"
                 : "=r"(r0), "=r"(r1), "=r"(r2), "=r"(r3) : "r"(addr));
}
__device__ __forceinline__ void mma16816(float* d,
    uint32_t a0, uint32_t a1, uint32_t a2, uint32_t a3,
    uint32_t b0, uint32_t b1)
{
    asm volatile(
        "mma.sync.aligned.m16n8k16.row.col.f32.bf16.bf16.f32 "
        "{%0,%1,%2,%3}, {%4,%5,%6,%7}, {%8,%9}, {%0,%1,%2,%3};"
        : "+f"(d[0]), "+f"(d[1]), "+f"(d[2]), "+f"(d[3])
        : "r"(a0), "r"(a1), "r"(a2), "r"(a3), "r"(b0), "r"(b1));
}

// ---------------- weight pre-split ----------------
__global__ void split_kernel(const float* __restrict__ s,
                             __nv_bfloat16* __restrict__ h,
                             __nv_bfloat16* __restrict__ l, long n4)
{
    long stride = (long)gridDim.x * blockDim.x;
    for (long i = (long)blockIdx.x * blockDim.x + threadIdx.x; i < n4; i += stride) {
        float4 v = ((const float4*)s)[i];
        uint2 H, L;
        H.x = pack2(v.x, v.y, L.x);
        H.y = pack2(v.z, v.w, L.y);
        ((uint2*)h)[i] = H;
        ((uint2*)l)[i] = L;
    }
}

// ---------------- embedding ----------------
__global__ void embed_kernel(const int* __restrict__ idx,
                             const float* __restrict__ wte,
                             const float* __restrict__ wpe,
                             float* __restrict__ x)
{
    int m = blockIdx.x;
    int t = m & (TT-1);
    int tok = idx[m];
    const float* we = wte + (size_t)tok * CC;
    const float* wp = wpe + (size_t)t * CC;
    float* xr = x + (size_t)m * CC;
    for (int c = threadIdx.x; c < CC; c += blockDim.x)
        xr[c] = we[c] + wp[c];
}

// ---------------- layernorm (warp-shuffle reductions) ----------
__global__ void ln_kernel(const float* __restrict__ x,
                          const float* __restrict__ w,
                          const float* __restrict__ b,
                          __nv_bfloat16* __restrict__ yh,
                          __nv_bfloat16* __restrict__ yl)
{
    __shared__ float red[16];
    int row  = blockIdx.x;
    int tid  = threadIdx.x;
    int lane = tid & 31;
    int warp = tid >> 5;
    const float* xr = x + (size_t)row * CC;

    float v0 = xr[tid], v1 = xr[tid+256], v2 = xr[tid+512];
    float s = v0 + v1 + v2;
    #pragma unroll
    for (int o = 16; o; o >>= 1) s += __shfl_xor_sync(0xffffffffu, s, o);
    if (!lane) red[warp] = s;
    __syncthreads();
    float mu = (red[0]+red[1]+red[2]+red[3]+red[4]+red[5]+red[6]+red[7]) * (1.0f/CC);

    float d0 = v0-mu, d1 = v1-mu, d2 = v2-mu;
    float q = d0*d0 + d1*d1 + d2*d2;
    #pragma unroll
    for (int o = 16; o; o >>= 1) q += __shfl_xor_sync(0xffffffffu, q, o);
    if (!lane) red[8+warp] = q;
    __syncthreads();
    float rstd = rsqrtf((red[8]+red[9]+red[10]+red[11]+red[12]+red[13]+red[14]+red[15])
                        * (1.0f/CC) + 1e-5f);

    size_t base = (size_t)row * CC;
    #pragma unroll
    for (int j = 0; j < 3; j++) {
        int c = tid + j*256;
        float v = (j==0?d0:(j==1?d1:d2))*rstd*w[c] + b[c];
        __nv_bfloat16 hv = __float2bfloat16(v);
        yh[base+c] = hv;
        yl[base+c] = __float2bfloat16(v - __bfloat162float(hv));
    }
}

// ---------------- split-bf16 HMMA GEMM, ldmatrix + 3-stage cp.async ----------
#define BKG   32
#define TILEB 8192
#define STAGEB (4*TILEB)
#define GSMEM (3*STAGEB)

template<bool GELU, bool RES, bool OUTSPLIT>
__global__ void __launch_bounds__(256)
gemm_hmma(const __nv_bfloat16* __restrict__ Xh, const __nv_bfloat16* __restrict__ Xl,
          const __nv_bfloat16* __restrict__ Wh, const __nv_bfloat16* __restrict__ Wl,
          const float* __restrict__ bias, const float* __restrict__ res,
          float* __restrict__ Y,
          __nv_bfloat16* __restrict__ Yh, __nv_bfloat16* __restrict__ Yl,
          int M, int N, int K)
{
    extern __shared__ char sm[];
    const uint32_t sb = smem_u32(sm);

    const int tid  = threadIdx.x;
    const int lane = tid & 31;
    const int warp = tid >> 5;
    const int wm   = warp & 1;
    const int wn   = warp >> 1;
    const int g    = lane >> 2;
    const int tg   = lane & 3;
    const int bm   = blockIdx.x * 128;
    const int bn   = blockIdx.y * 128;

    float d[4][4][4];
    #pragma unroll
    for (int i = 0; i < 4; i++)
        #pragma unroll
        for (int j = 0; j < 4; j++) {
            d[i][j][0]=0.f; d[i][j][1]=0.f; d[i][j][2]=0.f; d[i][j][3]=0.f;
        }

    const int lr  = tid >> 1;
    const int lcb = (tid & 1) * 2;
    const __nv_bfloat16* xh_p = Xh + (size_t)(bm + lr)*K;
    const __nv_bfloat16* xl_p = Xl + (size_t)(bm + lr)*K;
    const __nv_bfloat16* wh_p = Wh + (size_t)(bn + lr)*K;
    const __nv_bfloat16* wl_p = Wl + (size_t)(bn + lr)*K;
    const int rsw = (lr >> 1) & 3;
    uint32_t so[2];
    #pragma unroll
    for (int i = 0; i < 2; i++)
        so[i] = (uint32_t)(lr*64 + (((lcb+i) ^ rsw) << 4));

    uint32_t a_off[4][2], b_off[2][2];
    {
        int arow = wm*64 + (lane & 15);
        int ln16 = lane >> 4;
        #pragma unroll
        for (int fm = 0; fm < 4; fm++) {
            int r = arow + fm*16;
            #pragma unroll
            for (int ks = 0; ks < 2; ks++) {
                int c = ks*2 + ln16;
                a_off[fm][ks] = (uint32_t)(r*64 + ((c ^ ((r>>1)&3)) << 4));
            }
        }
        int q = lane >> 3;
        int brow = wn*32 + ((q >> 1) << 3) + (lane & 7);
        int cadd = q & 1;
        #pragma unroll
        for (int fnp = 0; fnp < 2; fnp++) {
            int r = brow + fnp*16;
            #pragma unroll
            for (int ks = 0; ks < 2; ks++) {
                int c = ks*2 + cadd;
                b_off[fnp][ks] = (uint32_t)(r*64 + ((c ^ ((r>>1)&3)) << 4));
            }
        }
    }

    const int NT = K / BKG;

    #pragma unroll
    for (int s = 0; s < 2; s++) {
        uint32_t base = sb + (uint32_t)s * STAGEB;
        const int k0 = s * BKG;
        #pragma unroll
        for (int i = 0; i < 2; i++) {
            int c = lcb + i;
            cpasync16(base +            so[i], (const char*)(xh_p + k0) + c*16);
            cpasync16(base +   TILEB +  so[i], (const char*)(xl_p + k0) + c*16);
            cpasync16(base + 2*TILEB +  so[i], (const char*)(wh_p + k0) + c*16);
            cpasync16(base + 3*TILEB +  so[i], (const char*)(wl_p + k0) + c*16);
        }
        cp_commit();
    }

    int bufc = 0;
    for (int t = 0; t < NT; t++) {
        cp_wait<1>();
        __syncthreads();

        if (t + 2 < NT) {
            int bufs = bufc + 2; if (bufs >= 3) bufs -= 3;
            uint32_t base = sb + (uint32_t)bufs * STAGEB;
            const int k0 = (t+2) * BKG;
            #pragma unroll
            for (int i = 0; i < 2; i++) {
                int c = lcb + i;
                cpasync16(base +            so[i], (const char*)(xh_p + k0) + c*16);
                cpasync16(base +   TILEB +  so[i], (const char*)(xl_p + k0) + c*16);
                cpasync16(base + 2*TILEB +  so[i], (const char*)(wh_p + k0) + c*16);
                cpasync16(base + 3*TILEB +  so[i], (const char*)(wl_p + k0) + c*16);
            }
        }
        cp_commit();

        {
            uint32_t base = sb + (uint32_t)bufc * STAGEB;
            uint32_t aH = base, aL = base + TILEB;
            uint32_t bH = base + 2*TILEB, bL = base + 3*TILEB;

            #pragma unroll
            for (int ks = 0; ks < 2; ks++) {
                uint32_t ah[4][4], al[4][4], bh[4][2], bl[4][2];
                #pragma unroll
                for (int fm = 0; fm < 4; fm++) {
                    ldsm4(ah[fm][0], ah[fm][1], ah[fm][2], ah[fm][3], aH + a_off[fm][ks]);
                    ldsm4(al[fm][0], al[fm][1], al[fm][2], al[fm][3], aL + a_off[fm][ks]);
                }
                #pragma unroll
                for (int fnp = 0; fnp < 2; fnp++) {
                    uint32_t r0, r1, r2, r3;
                    ldsm4(r0, r1, r2, r3, bH + b_off[fnp][ks]);
                    bh[fnp*2][0]=r0; bh[fnp*2][1]=r1; bh[fnp*2+1][0]=r2; bh[fnp*2+1][1]=r3;
                    ldsm4(r0, r1, r2, r3, bL + b_off[fnp][ks]);
                    bl[fnp*2][0]=r0; bl[fnp*2][1]=r1; bl[fnp*2+1][0]=r2; bl[fnp*2+1][1]=r3;
                }
                #pragma unroll
                for (int fm = 0; fm < 4; fm++)
                    #pragma unroll
                    for (int fn = 0; fn < 4; fn++) {
                        mma16816(d[fm][fn], ah[fm][0],ah[fm][1],ah[fm][2],ah[fm][3],
                                 bh[fn][0], bh[fn][1]);
                        mma16816(d[fm][fn], al[fm][0],al[fm][1],al[fm][2],al[fm][3],
                                 bh[fn][0], bh[fn][1]);
                        mma16816(d[fm][fn], ah[fm][0],ah[fm][1],ah[fm][2],ah[fm][3],
                                 bl[fn][0], bl[fn][1]);
                    }
            }
        }
        bufc = (bufc + 1 == 3) ? 0 : bufc + 1;
    }

    #pragma unroll
    for (int fm = 0; fm < 4; fm++) {
        int mrow = bm + wm*64 + fm*16 + g;
        #pragma unroll
        for (int half = 0; half < 2; half++) {
            int m = mrow + half*8;
            #pragma unroll
            for (int fn = 0; fn < 4; fn++) {
                int n0 = bn + wn*32 + fn*8 + tg*2;
                float v0 = d[fm][fn][half*2+0];
                float v1 = d[fm][fn][half*2+1];
                if (bias) { v0 += bias[n0]; v1 += bias[n0+1]; }
                if (GELU) { v0 = gelu_tanh(v0); v1 = gelu_tanh(v1); }
                if (RES) {
                    float2 rv = *(const float2*)&res[(size_t)m*N + n0];
                    v0 += rv.x; v1 += rv.y;
                }
                if (OUTSPLIT) {
                    uint32_t lo;
                    uint32_t hi = pack2(v0, v1, lo);
                    *(uint32_t*)&Yh[(size_t)m*N + n0] = hi;
                    *(uint32_t*)&Yl[(size_t)m*N + n0] = lo;
                } else {
                    float2 o2; o2.x = v0; o2.y = v1;
                    *(float2*)&Y[(size_t)m*N + n0] = o2;
                }
            }
        }
    }
}

// ---------------- tensor-core flash attention ----------------
// 128 q/CTA, 64-key tiles, 8 warps x 16 q-rows. Split-bf16 (3-term) for
// both QK^T and P*V, fp32 softmax (ex2.approx, log2e folded into Q scale).
// smem 32KB: Q staging [128][64]bf16 h/l overlaid by Kh/Kl/Vh/Vl [64][64].
__global__ void __launch_bounds__(256)
attn_tc(const float* __restrict__ qkv,
        __nv_bfloat16* __restrict__ yh, __nv_bfloat16* __restrict__ yl)
{
    __shared__ char smem[32768];
    const uint32_t sb = smem_u32(smem);
    const int tid  = threadIdx.x;
    const int lane = tid & 31;
    const int w    = tid >> 5;
    const int g    = lane >> 2;
    const int tg   = lane & 3;
    const int qt   = gridDim.x - 1 - blockIdx.x;   // heavy tiles first
    const int h    = blockIdx.y;
    const int b    = blockIdx.z;
    const int q0   = qt * 128;

    const float SC = 0.18033688011112042f;   // 0.125 * log2(e)

    // ---- stage Q (scaled, split) ----
    {
        int r  = tid >> 1;
        int dh = (tid & 1) * 32;
        const float* src = qkv + (size_t)(b*TT + q0 + r)*C3 + h*DD + dh;
        #pragma unroll
        for (int cc = 0; cc < 4; cc++) {
            float4 v0 = *(const float4*)(src + cc*8);
            float4 v1 = *(const float4*)(src + cc*8 + 4);
            uint4 Hc, Lc;
            Hc.x = pack2(v0.x*SC, v0.y*SC, Lc.x);
            Hc.y = pack2(v0.z*SC, v0.w*SC, Lc.y);
            Hc.z = pack2(v1.x*SC, v1.y*SC, Lc.z);
            Hc.w = pack2(v1.z*SC, v1.w*SC, Lc.w);
            int c = (dh >> 3) + cc;
            uint32_t off = (uint32_t)(r*128 + ((c ^ (r & 7)) << 4));
            *(uint4*)(smem + off)         = Hc;
            *(uint4*)(smem + 16384 + off) = Lc;
        }
    }
    __syncthreads();

    // ---- Q fragments to registers ----
    uint32_t qh[4][4], ql[4][4];
    #pragma unroll
    for (int kk = 0; kk < 4; kk++) {
        int row = w*16 + (lane & 15);
        int c   = kk*2 + (lane >> 4);
        uint32_t off = (uint32_t)(row*128 + ((c ^ (row & 7)) << 4));
        ldsm4(qh[kk][0], qh[kk][1], qh[kk][2], qh[kk][3], sb + off);
        ldsm4(ql[kk][0], ql[kk][1], ql[kk][2], ql[kk][3], sb + 16384 + off);
    }

    float o[8][4];
    #pragma unroll
    for (int j = 0; j < 8; j++) { o[j][0]=0.f; o[j][1]=0.f; o[j][2]=0.f; o[j][3]=0.f; }
    float mrow0 = -1e30f, mrow1 = -1e30f, lrow0 = 0.f, lrow1 = 0.f;

    const int qrow0 = q0 + w*16 + g;
    const int nk  = (q0 + 128) >> 6;
    const int nkw = ((q0 + w*16 + 15) >> 6) + 1;

    const uint32_t KH_ = 0u, KL_ = 8192u, VH_ = 16384u, VL_ = 24576u;

    for (int kt = 0; kt < nk; kt++) {
        __syncthreads();   // prev compute done before overwriting K/V (also guards Q frags at kt=0)

        // ---- load + split K,V tile ----
        {
            int r  = tid >> 2;
            int dq = (tid & 3) * 16;
            const float* kr = qkv + (size_t)(b*TT + kt*64 + r)*C3 + CC + h*DD + dq;
            const float* vr = kr + CC;
            #pragma unroll
            for (int half = 0; half < 2; half++) {
                int c = (dq >> 3) + half;
                uint32_t off = (uint32_t)(r*128 + ((c ^ (r & 7)) << 4));
                float4 k0 = *(const float4*)(kr + half*8);
                float4 k1 = *(const float4*)(kr + half*8 + 4);
                uint4 Hc, Lc;
                Hc.x = pack2(k0.x, k0.y, Lc.x);
                Hc.y = pack2(k0.z, k0.w, Lc.y);
                Hc.z = pack2(k1.x, k1.y, Lc.z);
                Hc.w = pack2(k1.z, k1.w, Lc.w);
                *(uint4*)(smem + KH_ + off) = Hc;
                *(uint4*)(smem + KL_ + off) = Lc;
                float4 w0 = *(const float4*)(vr + half*8);
                float4 w1 = *(const float4*)(vr + half*8 + 4);
                Hc.x = pack2(w0.x, w0.y, Lc.x);
                Hc.y = pack2(w0.z, w0.w, Lc.y);
                Hc.z = pack2(w1.x, w1.y, Lc.z);
                Hc.w = pack2(w1.z, w1.w, Lc.w);
                *(uint4*)(smem + VH_ + off) = Hc;
                *(uint4*)(smem + VL_ + off) = Lc;
            }
        }
        __syncthreads();

        if (kt >= nkw) continue;   // fully-masked for this warp; barriers already hit

        // ---- S = Q K^T (3-term split) ----
        float s[8][4];
        #pragma unroll
        for (int j = 0; j < 8; j++) { s[j][0]=0.f; s[j][1]=0.f; s[j][2]=0.f; s[j][3]=0.f; }

        #pragma unroll
        for (int kk = 0; kk < 4; kk++) {
            int q4 = lane >> 3;
            #pragma unroll
            for (int jj = 0; jj < 4; jj++) {
                int row = jj*16 + ((q4 >> 1) << 3) + (lane & 7);
                int c   = kk*2 + (q4 & 1);
                uint32_t off = (uint32_t)(row*128 + ((c ^ (row & 7)) << 4));
                uint32_t h0,h1,h2,h3, l0,l1,l2,l3;
                ldsm4(h0, h1, h2, h3, sb + KH_ + off);
                ldsm4(l0, l1, l2, l3, sb + KL_ + off);
                mma16816(s[2*jj  ], qh[kk][0],qh[kk][1],qh[kk][2],qh[kk][3], h0, h1);
                mma16816(s[2*jj  ], ql[kk][0],ql[kk][1],ql[kk][2],ql[kk][3], h0, h1);
                mma16816(s[2*jj  ], qh[kk][0],qh[kk][1],qh[kk][2],qh[kk][3], l0, l1);
                mma16816(s[2*jj+1], qh[kk][0],qh[kk][1],qh[kk][2],qh[kk][3], h2, h3);
                mma16816(s[2*jj+1], ql[kk][0],ql[kk][1],ql[kk][2],ql[kk][3], h2, h3);
                mma16816(s[2*jj+1], qh[kk][0],qh[kk][1],qh[kk][2],qh[kk][3], l2, l3);
            }
        }

        // ---- causal mask ----
        if (kt*64 + 63 > q0 + w*16) {
            #pragma unroll
            for (int j = 0; j < 8; j++) {
                int c0 = kt*64 + j*8 + 2*tg;
                if (c0     > qrow0)     s[j][0] = -1e30f;
                if (c0 + 1 > qrow0)     s[j][1] = -1e30f;
                if (c0     > qrow0 + 8) s[j][2] = -1e30f;
                if (c0 + 1 > qrow0 + 8) s[j][3] = -1e30f;
            }
        }

        // ---- online softmax (log2 domain) ----
        float mx0 = -1e30f, mx1 = -1e30f;
        #pragma unroll
        for (int j = 0; j < 8; j++) {
            mx0 = fmaxf(mx0, fmaxf(s[j][0], s[j][1]));
            mx1 = fmaxf(mx1, fmaxf(s[j][2], s[j][3]));
        }
        mx0 = fmaxf(mx0, __shfl_xor_sync(0xffffffffu, mx0, 1));
        mx0 = fmaxf(mx0, __shfl_xor_sync(0xffffffffu, mx0, 2));
        mx1 = fmaxf(mx1, __shfl_xor_sync(0xffffffffu, mx1, 1));
        mx1 = fmaxf(mx1, __shfl_xor_sync(0xffffffffu, mx1, 2));

        float mn0 = fmaxf(mrow0, mx0), mn1 = fmaxf(mrow1, mx1);
        float a0  = ex2f(mrow0 - mn0), a1  = ex2f(mrow1 - mn1);
        float ls0 = 0.f, ls1 = 0.f;
        #pragma unroll
        for (int j = 0; j < 8; j++) {
            s[j][0] = ex2f(s[j][0] - mn0);  ls0 += s[j][0];
            s[j][1] = ex2f(s[j][1] - mn0);  ls0 += s[j][1];
            s[j][2] = ex2f(s[j][2] - mn1);  ls1 += s[j][2];
            s[j][3] = ex2f(s[j][3] - mn1);  ls1 += s[j][3];
        }
        ls0 += __shfl_xor_sync(0xffffffffu, ls0, 1);
        ls0 += __shfl_xor_sync(0xffffffffu, ls0, 2);
        ls1 += __shfl_xor_sync(0xffffffffu, ls1, 1);
        ls1 += __shfl_xor_sync(0xffffffffu, ls1, 2);
        lrow0 = lrow0*a0 + ls0;  lrow1 = lrow1*a1 + ls1;
        mrow0 = mn0;  mrow1 = mn1;
        #pragma unroll
        for (int j = 0; j < 8; j++) {
            o[j][0] *= a0; o[j][1] *= a0; o[j][2] *= a1; o[j][3] *= a1;
        }

        // ---- pack P in place: s[] reinterpreted as bf16x2 hi/lo A-fragments ----
        uint32_t* sp = (uint32_t*)s;
        #pragma unroll
        for (int kk = 0; kk < 4; kk++) {
            uint32_t lo;
            uint32_t h0 = pack2(s[2*kk][0],   s[2*kk][1],   lo);
            sp[kk*8+0] = h0; sp[kk*8+1] = lo;
            uint32_t h1 = pack2(s[2*kk][2],   s[2*kk][3],   lo);
            sp[kk*8+2] = h1; sp[kk*8+3] = lo;
            uint32_t h2 = pack2(s[2*kk+1][0], s[2*kk+1][1], lo);
            sp[kk*8+4] = h2; sp[kk*8+5] = lo;
            uint32_t h3 = pack2(s[2*kk+1][2], s[2*kk+1][3], lo);
            sp[kk*8+6] = h3; sp[kk*8+7] = lo;
        }

        // ---- O += P V (3-term split) ----
        #pragma unroll
        for (int kk = 0; kk < 4; kk++) {
            uint32_t pa0 = sp[kk*8+0], pa1 = sp[kk*8+2], pa2 = sp[kk*8+4], pa3 = sp[kk*8+6];
            uint32_t pb0 = sp[kk*8+1], pb1 = sp[kk*8+3], pb2 = sp[kk*8+5], pb3 = sp[kk*8+7];
            int tl = lane >> 3;
            #pragma unroll
            for (int jj = 0; jj < 4; jj++) {
                int row = kk*16 + ((tl & 1) << 3) + (lane & 7);
                int c   = jj*2 + (tl >> 1);
                uint32_t off = (uint32_t)(row*128 + ((c ^ (row & 7)) << 4));
                uint32_t v0,v1,v2,v3, u0,u1,u2,u3;
                ldsm4t(v0, v1, v2, v3, sb + VH_ + off);
                ldsm4t(u0, u1, u2, u3, sb + VL_ + off);
                mma16816(o[2*jj  ], pa0, pa1, pa2, pa3, v0, v1);
                mma16816(o[2*jj  ], pb0, pb1, pb2, pb3, v0, v1);
                mma16816(o[2*jj  ], pa0, pa1, pa2, pa3, u0, u1);
                mma16816(o[2*jj+1], pa0, pa1, pa2, pa3, v2, v3);
                mma16816(o[2*jj+1], pb0, pb1, pb2, pb3, v2, v3);
                mma16816(o[2*jj+1], pa0, pa1, pa2, pa3, u2, u3);
            }
        }
    }

    // ---- epilogue ----
    float inv0 = 1.0f / lrow0, inv1 = 1.0f / lrow1;
    #pragma unroll
    for (int j = 0; j < 8; j++) {
        uint32_t lo;
        size_t oidx = (size_t)(b*TT + qrow0)*CC + h*DD + j*8 + 2*tg;
        uint32_t hi = pack2(o[j][0]*inv0, o[j][1]*inv0, lo);
        *(uint32_t*)&yh[oidx] = hi;
        *(uint32_t*)&yl[oidx] = lo;
        oidx += (size_t)8*CC;
        hi = pack2(o[j][2]*inv1, o[j][3]*inv1, lo);
        *(uint32_t*)&yh[oidx] = hi;
        *(uint32_t*)&yl[oidx] = lo;
    }
}

// ---------------- launch ----------------
extern "C" void kernel_launch(void* const* d_in, const int* in_sizes, int n_in,
                              void* d_out, int out_size)
{
    (void)in_sizes; (void)n_in; (void)out_size;
    const int*   idx     = (const int*)  d_in[0];
    const float* wte     = (const float*)d_in[1];
    const float* wpe     = (const float*)d_in[2];
    const float* ln1w    = (const float*)d_in[3];
    const float* ln1b    = (const float*)d_in[4];
    const float* qkvw    = (const float*)d_in[5];
    const float* qkvb    = (const float*)d_in[6];
    const float* projw   = (const float*)d_in[7];
    const float* projb   = (const float*)d_in[8];
    const float* ln2w    = (const float*)d_in[9];
    const float* ln2b    = (const float*)d_in[10];
    const float* fcw     = (const float*)d_in[11];
    const float* fcb     = (const float*)d_in[12];
    const float* fcprojw = (const float*)d_in[13];
    const float* fcprojb = (const float*)d_in[14];
    const float* lnfw    = (const float*)d_in[15];
    const float* lnfb    = (const float*)d_in[16];
    float* out = (float*)d_out;

    float *x, *qkv;
    __nv_bfloat16 *lnh, *lnl, *atth, *attl, *acth, *actl;
    __nv_bfloat16 *qkvwh, *qkvwl, *projwh, *projwl, *fcwh, *fcwl, *fcpwh, *fcpwl, *wteh, *wtel;
    cudaGetSymbolAddress((void**)&x,    g_x);
    cudaGetSymbolAddress((void**)&qkv,  g_qkv);
    cudaGetSymbolAddress((void**)&lnh,  g_ln_h);   cudaGetSymbolAddress((void**)&lnl,  g_ln_l);
    cudaGetSymbolAddress((void**)&atth, g_att_h);  cudaGetSymbolAddress((void**)&attl, g_att_l);
    cudaGetSymbolAddress((void**)&acth, g_act_h);  cudaGetSymbolAddress((void**)&actl, g_act_l);
    cudaGetSymbolAddress((void**)&qkvwh, g_qkvw_h); cudaGetSymbolAddress((void**)&qkvwl, g_qkvw_l);
    cudaGetSymbolAddress((void**)&projwh,g_projw_h);cudaGetSymbolAddress((void**)&projwl,g_projw_l);
    cudaGetSymbolAddress((void**)&fcwh, g_fcw_h);  cudaGetSymbolAddress((void**)&fcwl, g_fcw_l);
    cudaGetSymbolAddress((void**)&fcpwh,g_fcpw_h); cudaGetSymbolAddress((void**)&fcpwl,g_fcpw_l);
    cudaGetSymbolAddress((void**)&wteh, g_wte_h);  cudaGetSymbolAddress((void**)&wtel, g_wte_l);

    cudaFuncSetAttribute(gemm_hmma<false,false,false>, cudaFuncAttributeMaxDynamicSharedMemorySize, GSMEM);
    cudaFuncSetAttribute(gemm_hmma<false,true ,false>, cudaFuncAttributeMaxDynamicSharedMemorySize, GSMEM);
    cudaFuncSetAttribute(gemm_hmma<true ,false,true >, cudaFuncAttributeMaxDynamicSharedMemorySize, GSMEM);

    const int SB = 1184;
    split_kernel<<<SB, 256>>>(qkvw,    qkvwh,  qkvwl,  (long)LL*C3*CC/4);
    split_kernel<<<SB, 256>>>(projw,   projwh, projwl, (long)LL*CC*CC/4);
    split_kernel<<<SB, 256>>>(fcw,     fcwh,   fcwl,   (long)LL*C4*CC/4);
    split_kernel<<<SB, 256>>>(fcprojw, fcpwh,  fcpwl,  (long)LL*CC*C4/4);
    split_kernel<<<SB, 256>>>(wte,     wteh,   wtel,   (long)VP*CC/4);

    embed_kernel<<<MROWS, 256>>>(idx, wte, wpe, x);

    for (int l = 0; l < LL; l++) {
        ln_kernel<<<MROWS, 256>>>(x, ln1w + l*CC, ln1b + l*CC, lnh, lnl);

        gemm_hmma<false,false,false><<<dim3(MROWS/128, C3/128), 256, GSMEM>>>(
            lnh, lnl, qkvwh + (size_t)l*C3*CC, qkvwl + (size_t)l*C3*CC,
            qkvb + (size_t)l*C3, nullptr, qkv, nullptr, nullptr, MROWS, C3, CC);

        attn_tc<<<dim3(TT/128, HH, BATCH), 256>>>(qkv, atth, attl);

        gemm_hmma<false,true,false><<<dim3(MROWS/128, CC/128), 256, GSMEM>>>(
            atth, attl, projwh + (size_t)l*CC*CC, projwl + (size_t)l*CC*CC,
            projb + (size_t)l*CC, x, x, nullptr, nullptr, MROWS, CC, CC);

        ln_kernel<<<MROWS, 256>>>(x, ln2w + l*CC, ln2b + l*CC, lnh, lnl);

        gemm_hmma<true,false,true><<<dim3(MROWS/128, C4/128), 256, GSMEM>>>(
            lnh, lnl, fcwh + (size_t)l*C4*CC, fcwl + (size_t)l*C4*CC,
            fcb + (size_t)l*C4, nullptr, nullptr, acth, actl, MROWS, C4, CC);

        gemm_hmma<false,true,false><<<dim3(MROWS/128, CC/128), 256, GSMEM>>>(
            acth, actl, fcpwh + (size_t)l*CC*C4, fcpwl + (size_t)l*CC*C4,
            fcprojb + (size_t)l*CC, x, x, nullptr, nullptr, MROWS, CC, C4);
    }

    ln_kernel<<<MROWS, 256>>>(x, lnfw, lnfb, lnh, lnl);

    gemm_hmma<false,false,false><<<dim3(MROWS/128, VP/128), 256, GSMEM>>>(
        lnh, lnl, wteh, wtel, nullptr, nullptr, out, nullptr, nullptr, MROWS, VP, CC);
}

// round 9
// speedup vs baseline: 4.8781x; 1.3451x over previous
#include <cuda_runtime.h>
#include <cuda_bf16.h>
#include <cuda_fp16.h>
#include <math.h>
#include <stdint.h>

// ---------------- problem constants ----------------
#define BATCH 2
#define TT    1024
#define CC    768
#define HH    12
#define DD    64
#define LL    12
#define MROWS (BATCH*TT)      // 2048
#define C3    (3*CC)          // 2304
#define C4    (4*CC)          // 3072
#define VP    50304

// ---------------- scratch (device globals) ----------
__device__ float g_x  [MROWS*CC];
__device__ float g_qkv[MROWS*C3];

// fp16 activations (hi only; activation-lo term dropped)
__device__ __half g_ln [MROWS*CC];
__device__ __half g_att[MROWS*CC];
__device__ __half g_act[MROWS*C4];

// fp16 weights, split hi/lo
__device__ __half g_qkvw_h [(size_t)LL*C3*CC], g_qkvw_l [(size_t)LL*C3*CC];
__device__ __half g_projw_h[(size_t)LL*CC*CC], g_projw_l[(size_t)LL*CC*CC];
__device__ __half g_fcw_h  [(size_t)LL*C4*CC], g_fcw_l  [(size_t)LL*C4*CC];
__device__ __half g_fcpw_h [(size_t)LL*CC*C4], g_fcpw_l [(size_t)LL*CC*C4];
__device__ __half g_wte_h  [(size_t)VP*CC],    g_wte_l  [(size_t)VP*CC];

// ---------------- small helpers ----------------
// bf16 split pack (attention internals)
__device__ __forceinline__ uint32_t pack2(float x, float y, uint32_t &lo)
{
    __nv_bfloat16 xh = __float2bfloat16(x);
    __nv_bfloat16 yh = __float2bfloat16(y);
    __nv_bfloat162 H; H.x = xh; H.y = yh;
    __nv_bfloat162 L; L.x = __float2bfloat16(x - __bfloat162float(xh));
    L.y = __float2bfloat16(y - __bfloat162float(yh));
    lo = *reinterpret_cast<const uint32_t*>(&L);
    return *reinterpret_cast<const uint32_t*>(&H);
}
// fp16 pair pack
__device__ __forceinline__ uint32_t packh2(float x, float y)
{
    __half2 H; H.x = __float2half(x); H.y = __float2half(y);
    return *reinterpret_cast<const uint32_t*>(&H);
}
// fp16 split pack (weights)
__device__ __forceinline__ uint32_t packh2_split(float x, float y, uint32_t &lo)
{
    __half xh = __float2half(x);
    __half yh = __float2half(y);
    __half2 H; H.x = xh; H.y = yh;
    __half2 L; L.x = __float2half(x - __half2float(xh));
    L.y = __float2half(y - __half2float(yh));
    lo = *reinterpret_cast<const uint32_t*>(&L);
    return *reinterpret_cast<const uint32_t*>(&H);
}

__device__ __forceinline__ float gelu_tanh(float x) {
    float x3 = x*x*x;
    return 0.5f * x * (1.0f + tanhf(0.7978845608028654f * (x + 0.044715f * x3)));
}

__device__ __forceinline__ float ex2f(float x) {
    float y;
    asm("ex2.approx.f32 %0, %1;" : "=f"(y) : "f"(x));
    return y;
}

__device__ __forceinline__ uint32_t smem_u32(const void* p) {
    uint32_t a;
    asm("{ .reg .u64 t; cvta.to.shared.u64 t, %1; cvt.u32.u64 %0, t; }"
        : "=r"(a) : "l"(p));
    return a;
}
__device__ __forceinline__ void cpasync16(uint32_t dst, const void* src) {
    asm volatile("cp.async.cg.shared.global [%0], [%1], 16;"
                 :: "r"(dst), "l"(__cvta_generic_to_global(src)));
}
__device__ __forceinline__ void cp_commit() {
    asm volatile("cp.async.commit_group;");
}
template<int N>
__device__ __forceinline__ void cp_wait() {
    asm volatile("cp.async.wait_group %0;" :: "n"(N));
}
__device__ __forceinline__ void ldsm4(uint32_t& r0, uint32_t& r1,
                                      uint32_t& r2, uint32_t& r3, uint32_t addr) {
    asm volatile("ldmatrix.sync.aligned.m8n8.x4.shared.b16 {%0,%1,%2,%3}, [%4];"
                 : "=r"(r0), "=r"(r1), "=r"(r2), "=r"(r3) : "r"(addr));
}
__device__ __forceinline__ void ldsm4t(uint32_t& r0, uint32_t& r1,
                                       uint32_t& r2, uint32_t& r3, uint32_t addr) {
    asm volatile("ldmatrix.sync.aligned.m8n8.x4.trans.shared.b16 {%0,%1,%2,%3}, [%4];"
                 : "=r"(r0), "=r"(r1), "=r"(r2), "=r"(r3) : "r"(addr));
}
// bf16 mma (attention)
__device__ __forceinline__ void mma16816(float* d,
    uint32_t a0, uint32_t a1, uint32_t a2, uint32_t a3,
    uint32_t b0, uint32_t b1)
{
    asm volatile(
        "mma.sync.aligned.m16n8k16.row.col.f32.bf16.bf16.f32 "
        "{%0,%1,%2,%3}, {%4,%5,%6,%7}, {%8,%9}, {%0,%1,%2,%3};"
        : "+f"(d[0]), "+f"(d[1]), "+f"(d[2]), "+f"(d[3])
        : "r"(a0), "r"(a1), "r"(a2), "r"(a3), "r"(b0), "r"(b1));
}
// fp16 mma (GEMM)
__device__ __forceinline__ void mma16816h(float* d,
    uint32_t a0, uint32_t a1, uint32_t a2, uint32_t a3,
    uint32_t b0, uint32_t b1)
{
    asm volatile(
        "mma.sync.aligned.m16n8k16.row.col.f32.f16.f16.f32 "
        "{%0,%1,%2,%3}, {%4,%5,%6,%7}, {%8,%9}, {%0,%1,%2,%3};"
        : "+f"(d[0]), "+f"(d[1]), "+f"(d[2]), "+f"(d[3])
        : "r"(a0), "r"(a1), "r"(a2), "r"(a3), "r"(b0), "r"(b1));
}

// ---------------- weight pre-split (fp32 -> fp16 hi/lo) ----------------
__global__ void split_kernel(const float* __restrict__ s,
                             __half* __restrict__ h,
                             __half* __restrict__ l, long n4)
{
    long stride = (long)gridDim.x * blockDim.x;
    for (long i = (long)blockIdx.x * blockDim.x + threadIdx.x; i < n4; i += stride) {
        float4 v = ((const float4*)s)[i];
        uint2 H, L;
        H.x = packh2_split(v.x, v.y, L.x);
        H.y = packh2_split(v.z, v.w, L.y);
        ((uint2*)h)[i] = H;
        ((uint2*)l)[i] = L;
    }
}

// ---------------- embedding ----------------
__global__ void embed_kernel(const int* __restrict__ idx,
                             const float* __restrict__ wte,
                             const float* __restrict__ wpe,
                             float* __restrict__ x)
{
    int m = blockIdx.x;
    int t = m & (TT-1);
    int tok = idx[m];
    const float* we = wte + (size_t)tok * CC;
    const float* wp = wpe + (size_t)t * CC;
    float* xr = x + (size_t)m * CC;
    for (int c = threadIdx.x; c < CC; c += blockDim.x)
        xr[c] = we[c] + wp[c];
}

// ---------------- layernorm -> fp16 ----------
__global__ void ln_kernel(const float* __restrict__ x,
                          const float* __restrict__ w,
                          const float* __restrict__ b,
                          __half* __restrict__ yh)
{
    __shared__ float red[16];
    int row  = blockIdx.x;
    int tid  = threadIdx.x;
    int lane = tid & 31;
    int warp = tid >> 5;
    const float* xr = x + (size_t)row * CC;

    float v0 = xr[tid], v1 = xr[tid+256], v2 = xr[tid+512];
    float s = v0 + v1 + v2;
    #pragma unroll
    for (int o = 16; o; o >>= 1) s += __shfl_xor_sync(0xffffffffu, s, o);
    if (!lane) red[warp] = s;
    __syncthreads();
    float mu = (red[0]+red[1]+red[2]+red[3]+red[4]+red[5]+red[6]+red[7]) * (1.0f/CC);

    float d0 = v0-mu, d1 = v1-mu, d2 = v2-mu;
    float q = d0*d0 + d1*d1 + d2*d2;
    #pragma unroll
    for (int o = 16; o; o >>= 1) q += __shfl_xor_sync(0xffffffffu, q, o);
    if (!lane) red[8+warp] = q;
    __syncthreads();
    float rstd = rsqrtf((red[8]+red[9]+red[10]+red[11]+red[12]+red[13]+red[14]+red[15])
                        * (1.0f/CC) + 1e-5f);

    size_t base = (size_t)row * CC;
    #pragma unroll
    for (int j = 0; j < 3; j++) {
        int c = tid + j*256;
        float v = (j==0?d0:(j==1?d1:d2))*rstd*w[c] + b[c];
        yh[base+c] = __float2half(v);
    }
}

// ---------------- fp16 2-product HMMA GEMM ----------
// Y = X @ W^T (+bias)(gelu)(+res). X fp16 (hi only), W fp16 hi+lo.
// D = X*Wh + X*Wl. CTA tile 128x128, BK=32, 8 warps (2x4), warp 64x32.
// smem: X(8KB) + Wh(8KB) + Wl(8KB) per stage, swizzle c ^= (r>>1)&3, 3 stages.
#define BKG   32
#define TILEB 8192
#define STAGEB (3*TILEB)      // X WH WL = 24KB
#define GSMEM (3*STAGEB)      // 73728

template<bool GELU, bool RES, bool OUTHALF>
__global__ void __launch_bounds__(256)
gemm_hmma(const __half* __restrict__ X,
          const __half* __restrict__ Wh, const __half* __restrict__ Wl,
          const float* __restrict__ bias, const float* __restrict__ res,
          float* __restrict__ Y, __half* __restrict__ Yh,
          int M, int N, int K)
{
    extern __shared__ char sm[];
    const uint32_t sb = smem_u32(sm);

    const int tid  = threadIdx.x;
    const int lane = tid & 31;
    const int warp = tid >> 5;
    const int wm   = warp & 1;
    const int wn   = warp >> 1;
    const int g    = lane >> 2;
    const int tg   = lane & 3;
    const int bm   = blockIdx.x * 128;
    const int bn   = blockIdx.y * 128;

    float d[4][4][4];
    #pragma unroll
    for (int i = 0; i < 4; i++)
        #pragma unroll
        for (int j = 0; j < 4; j++) {
            d[i][j][0]=0.f; d[i][j][1]=0.f; d[i][j][2]=0.f; d[i][j][3]=0.f;
        }

    const int lr  = tid >> 1;
    const int lcb = (tid & 1) * 2;
    const __half* x_p  = X  + (size_t)(bm + lr)*K;
    const __half* wh_p = Wh + (size_t)(bn + lr)*K;
    const __half* wl_p = Wl + (size_t)(bn + lr)*K;
    const int rsw = (lr >> 1) & 3;
    uint32_t so[2];
    #pragma unroll
    for (int i = 0; i < 2; i++)
        so[i] = (uint32_t)(lr*64 + (((lcb+i) ^ rsw) << 4));

    uint32_t a_off[4][2], b_off[2][2];
    {
        int arow = wm*64 + (lane & 15);
        int ln16 = lane >> 4;
        #pragma unroll
        for (int fm = 0; fm < 4; fm++) {
            int r = arow + fm*16;
            #pragma unroll
            for (int ks = 0; ks < 2; ks++) {
                int c = ks*2 + ln16;
                a_off[fm][ks] = (uint32_t)(r*64 + ((c ^ ((r>>1)&3)) << 4));
            }
        }
        int q = lane >> 3;
        int brow = wn*32 + ((q >> 1) << 3) + (lane & 7);
        int cadd = q & 1;
        #pragma unroll
        for (int fnp = 0; fnp < 2; fnp++) {
            int r = brow + fnp*16;
            #pragma unroll
            for (int ks = 0; ks < 2; ks++) {
                int c = ks*2 + cadd;
                b_off[fnp][ks] = (uint32_t)(r*64 + ((c ^ ((r>>1)&3)) << 4));
            }
        }
    }

    const int NT = K / BKG;

    #pragma unroll
    for (int s = 0; s < 2; s++) {
        uint32_t base = sb + (uint32_t)s * STAGEB;
        const int k0 = s * BKG;
        #pragma unroll
        for (int i = 0; i < 2; i++) {
            int c = lcb + i;
            cpasync16(base +            so[i], (const char*)(x_p  + k0) + c*16);
            cpasync16(base +   TILEB +  so[i], (const char*)(wh_p + k0) + c*16);
            cpasync16(base + 2*TILEB +  so[i], (const char*)(wl_p + k0) + c*16);
        }
        cp_commit();
    }

    int bufc = 0;
    for (int t = 0; t < NT; t++) {
        cp_wait<1>();
        __syncthreads();

        if (t + 2 < NT) {
            int bufs = bufc + 2; if (bufs >= 3) bufs -= 3;
            uint32_t base = sb + (uint32_t)bufs * STAGEB;
            const int k0 = (t+2) * BKG;
            #pragma unroll
            for (int i = 0; i < 2; i++) {
                int c = lcb + i;
                cpasync16(base +            so[i], (const char*)(x_p  + k0) + c*16);
                cpasync16(base +   TILEB +  so[i], (const char*)(wh_p + k0) + c*16);
                cpasync16(base + 2*TILEB +  so[i], (const char*)(wl_p + k0) + c*16);
            }
        }
        cp_commit();

        {
            uint32_t base = sb + (uint32_t)bufc * STAGEB;
            uint32_t aX = base;
            uint32_t bH = base + TILEB, bL = base + 2*TILEB;

            #pragma unroll
            for (int ks = 0; ks < 2; ks++) {
                uint32_t ah[4][4], bh[4][2], bl[4][2];
                #pragma unroll
                for (int fm = 0; fm < 4; fm++)
                    ldsm4(ah[fm][0], ah[fm][1], ah[fm][2], ah[fm][3], aX + a_off[fm][ks]);
                #pragma unroll
                for (int fnp = 0; fnp < 2; fnp++) {
                    uint32_t r0, r1, r2, r3;
                    ldsm4(r0, r1, r2, r3, bH + b_off[fnp][ks]);
                    bh[fnp*2][0]=r0; bh[fnp*2][1]=r1; bh[fnp*2+1][0]=r2; bh[fnp*2+1][1]=r3;
                    ldsm4(r0, r1, r2, r3, bL + b_off[fnp][ks]);
                    bl[fnp*2][0]=r0; bl[fnp*2][1]=r1; bl[fnp*2+1][0]=r2; bl[fnp*2+1][1]=r3;
                }
                #pragma unroll
                for (int fm = 0; fm < 4; fm++)
                    #pragma unroll
                    for (int fn = 0; fn < 4; fn++) {
                        mma16816h(d[fm][fn], ah[fm][0],ah[fm][1],ah[fm][2],ah[fm][3],
                                  bh[fn][0], bh[fn][1]);
                        mma16816h(d[fm][fn], ah[fm][0],ah[fm][1],ah[fm][2],ah[fm][3],
                                  bl[fn][0], bl[fn][1]);
                    }
            }
        }
        bufc = (bufc + 1 == 3) ? 0 : bufc + 1;
    }

    #pragma unroll
    for (int fm = 0; fm < 4; fm++) {
        int mrow = bm + wm*64 + fm*16 + g;
        #pragma unroll
        for (int half = 0; half < 2; half++) {
            int m = mrow + half*8;
            #pragma unroll
            for (int fn = 0; fn < 4; fn++) {
                int n0 = bn + wn*32 + fn*8 + tg*2;
                float v0 = d[fm][fn][half*2+0];
                float v1 = d[fm][fn][half*2+1];
                if (bias) { v0 += bias[n0]; v1 += bias[n0+1]; }
                if (GELU) { v0 = gelu_tanh(v0); v1 = gelu_tanh(v1); }
                if (RES) {
                    float2 rv = *(const float2*)&res[(size_t)m*N + n0];
                    v0 += rv.x; v1 += rv.y;
                }
                if (OUTHALF) {
                    *(uint32_t*)&Yh[(size_t)m*N + n0] = packh2(v0, v1);
                } else {
                    float2 o2; o2.x = v0; o2.y = v1;
                    *(float2*)&Y[(size_t)m*N + n0] = o2;
                }
            }
        }
    }
}

// ---------------- tensor-core flash attention (bf16 3-term, fp16 output) ----
__global__ void __launch_bounds__(256)
attn_tc(const float* __restrict__ qkv, __half* __restrict__ yh)
{
    __shared__ char smem[32768];
    const uint32_t sb = smem_u32(smem);
    const int tid  = threadIdx.x;
    const int lane = tid & 31;
    const int w    = tid >> 5;
    const int g    = lane >> 2;
    const int tg   = lane & 3;
    const int qt   = gridDim.x - 1 - blockIdx.x;
    const int h    = blockIdx.y;
    const int b    = blockIdx.z;
    const int q0   = qt * 128;

    const float SC = 0.18033688011112042f;   // 0.125 * log2(e)

    // ---- stage Q (scaled, split) ----
    {
        int r  = tid >> 1;
        int dh = (tid & 1) * 32;
        const float* src = qkv + (size_t)(b*TT + q0 + r)*C3 + h*DD + dh;
        #pragma unroll
        for (int cc = 0; cc < 4; cc++) {
            float4 v0 = *(const float4*)(src + cc*8);
            float4 v1 = *(const float4*)(src + cc*8 + 4);
            uint4 Hc, Lc;
            Hc.x = pack2(v0.x*SC, v0.y*SC, Lc.x);
            Hc.y = pack2(v0.z*SC, v0.w*SC, Lc.y);
            Hc.z = pack2(v1.x*SC, v1.y*SC, Lc.z);
            Hc.w = pack2(v1.z*SC, v1.w*SC, Lc.w);
            int c = (dh >> 3) + cc;
            uint32_t off = (uint32_t)(r*128 + ((c ^ (r & 7)) << 4));
            *(uint4*)(smem + off)         = Hc;
            *(uint4*)(smem + 16384 + off) = Lc;
        }
    }
    __syncthreads();

    uint32_t qh[4][4], ql[4][4];
    #pragma unroll
    for (int kk = 0; kk < 4; kk++) {
        int row = w*16 + (lane & 15);
        int c   = kk*2 + (lane >> 4);
        uint32_t off = (uint32_t)(row*128 + ((c ^ (row & 7)) << 4));
        ldsm4(qh[kk][0], qh[kk][1], qh[kk][2], qh[kk][3], sb + off);
        ldsm4(ql[kk][0], ql[kk][1], ql[kk][2], ql[kk][3], sb + 16384 + off);
    }

    float o[8][4];
    #pragma unroll
    for (int j = 0; j < 8; j++) { o[j][0]=0.f; o[j][1]=0.f; o[j][2]=0.f; o[j][3]=0.f; }
    float mrow0 = -1e30f, mrow1 = -1e30f, lrow0 = 0.f, lrow1 = 0.f;

    const int qrow0 = q0 + w*16 + g;
    const int nk  = (q0 + 128) >> 6;
    const int nkw = ((q0 + w*16 + 15) >> 6) + 1;

    const uint32_t KH_ = 0u, KL_ = 8192u, VH_ = 16384u, VL_ = 24576u;

    for (int kt = 0; kt < nk; kt++) {
        __syncthreads();

        {
            int r  = tid >> 2;
            int dq = (tid & 3) * 16;
            const float* kr = qkv + (size_t)(b*TT + kt*64 + r)*C3 + CC + h*DD + dq;
            const float* vr = kr + CC;
            #pragma unroll
            for (int half = 0; half < 2; half++) {
                int c = (dq >> 3) + half;
                uint32_t off = (uint32_t)(r*128 + ((c ^ (r & 7)) << 4));
                float4 k0 = *(const float4*)(kr + half*8);
                float4 k1 = *(const float4*)(kr + half*8 + 4);
                uint4 Hc, Lc;
                Hc.x = pack2(k0.x, k0.y, Lc.x);
                Hc.y = pack2(k0.z, k0.w, Lc.y);
                Hc.z = pack2(k1.x, k1.y, Lc.z);
                Hc.w = pack2(k1.z, k1.w, Lc.w);
                *(uint4*)(smem + KH_ + off) = Hc;
                *(uint4*)(smem + KL_ + off) = Lc;
                float4 w0 = *(const float4*)(vr + half*8);
                float4 w1 = *(const float4*)(vr + half*8 + 4);
                Hc.x = pack2(w0.x, w0.y, Lc.x);
                Hc.y = pack2(w0.z, w0.w, Lc.y);
                Hc.z = pack2(w1.x, w1.y, Lc.z);
                Hc.w = pack2(w1.z, w1.w, Lc.w);
                *(uint4*)(smem + VH_ + off) = Hc;
                *(uint4*)(smem + VL_ + off) = Lc;
            }
        }
        __syncthreads();

        if (kt >= nkw) continue;

        float s[8][4];
        #pragma unroll
        for (int j = 0; j < 8; j++) { s[j][0]=0.f; s[j][1]=0.f; s[j][2]=0.f; s[j][3]=0.f; }

        #pragma unroll
        for (int kk = 0; kk < 4; kk++) {
            int q4 = lane >> 3;
            #pragma unroll
            for (int jj = 0; jj < 4; jj++) {
                int row = jj*16 + ((q4 >> 1) << 3) + (lane & 7);
                int c   = kk*2 + (q4 & 1);
                uint32_t off = (uint32_t)(row*128 + ((c ^ (row & 7)) << 4));
                uint32_t h0,h1,h2,h3, l0,l1,l2,l3;
                ldsm4(h0, h1, h2, h3, sb + KH_ + off);
                ldsm4(l0, l1, l2, l3, sb + KL_ + off);
                mma16816(s[2*jj  ], qh[kk][0],qh[kk][1],qh[kk][2],qh[kk][3], h0, h1);
                mma16816(s[2*jj  ], ql[kk][0],ql[kk][1],ql[kk][2],ql[kk][3], h0, h1);
                mma16816(s[2*jj  ], qh[kk][0],qh[kk][1],qh[kk][2],qh[kk][3], l0, l1);
                mma16816(s[2*jj+1], qh[kk][0],qh[kk][1],qh[kk][2],qh[kk][3], h2, h3);
                mma16816(s[2*jj+1], ql[kk][0],ql[kk][1],ql[kk][2],ql[kk][3], h2, h3);
                mma16816(s[2*jj+1], qh[kk][0],qh[kk][1],qh[kk][2],qh[kk][3], l2, l3);
            }
        }

        if (kt*64 + 63 > q0 + w*16) {
            #pragma unroll
            for (int j = 0; j < 8; j++) {
                int c0 = kt*64 + j*8 + 2*tg;
                if (c0     > qrow0)     s[j][0] = -1e30f;
                if (c0 + 1 > qrow0)     s[j][1] = -1e30f;
                if (c0     > qrow0 + 8) s[j][2] = -1e30f;
                if (c0 + 1 > qrow0 + 8) s[j][3] = -1e30f;
            }
        }

        float mx0 = -1e30f, mx1 = -1e30f;
        #pragma unroll
        for (int j = 0; j < 8; j++) {
            mx0 = fmaxf(mx0, fmaxf(s[j][0], s[j][1]));
            mx1 = fmaxf(mx1, fmaxf(s[j][2], s[j][3]));
        }
        mx0 = fmaxf(mx0, __shfl_xor_sync(0xffffffffu, mx0, 1));
        mx0 = fmaxf(mx0, __shfl_xor_sync(0xffffffffu, mx0, 2));
        mx1 = fmaxf(mx1, __shfl_xor_sync(0xffffffffu, mx1, 1));
        mx1 = fmaxf(mx1, __shfl_xor_sync(0xffffffffu, mx1, 2));

        float mn0 = fmaxf(mrow0, mx0), mn1 = fmaxf(mrow1, mx1);
        float a0  = ex2f(mrow0 - mn0), a1  = ex2f(mrow1 - mn1);
        float ls0 = 0.f, ls1 = 0.f;
        #pragma unroll
        for (int j = 0; j < 8; j++) {
            s[j][0] = ex2f(s[j][0] - mn0);  ls0 += s[j][0];
            s[j][1] = ex2f(s[j][1] - mn0);  ls0 += s[j][1];
            s[j][2] = ex2f(s[j][2] - mn1);  ls1 += s[j][2];
            s[j][3] = ex2f(s[j][3] - mn1);  ls1 += s[j][3];
        }
        ls0 += __shfl_xor_sync(0xffffffffu, ls0, 1);
        ls0 += __shfl_xor_sync(0xffffffffu, ls0, 2);
        ls1 += __shfl_xor_sync(0xffffffffu, ls1, 1);
        ls1 += __shfl_xor_sync(0xffffffffu, ls1, 2);
        lrow0 = lrow0*a0 + ls0;  lrow1 = lrow1*a1 + ls1;
        mrow0 = mn0;  mrow1 = mn1;
        #pragma unroll
        for (int j = 0; j < 8; j++) {
            o[j][0] *= a0; o[j][1] *= a0; o[j][2] *= a1; o[j][3] *= a1;
        }

        uint32_t* sp = (uint32_t*)s;
        #pragma unroll
        for (int kk = 0; kk < 4; kk++) {
            uint32_t lo;
            uint32_t h0 = pack2(s[2*kk][0],   s[2*kk][1],   lo);
            sp[kk*8+0] = h0; sp[kk*8+1] = lo;
            uint32_t h1 = pack2(s[2*kk][2],   s[2*kk][3],   lo);
            sp[kk*8+2] = h1; sp[kk*8+3] = lo;
            uint32_t h2 = pack2(s[2*kk+1][0], s[2*kk+1][1], lo);
            sp[kk*8+4] = h2; sp[kk*8+5] = lo;
            uint32_t h3 = pack2(s[2*kk+1][2], s[2*kk+1][3], lo);
            sp[kk*8+6] = h3; sp[kk*8+7] = lo;
        }

        #pragma unroll
        for (int kk = 0; kk < 4; kk++) {
            uint32_t pa0 = sp[kk*8+0], pa1 = sp[kk*8+2], pa2 = sp[kk*8+4], pa3 = sp[kk*8+6];
            uint32_t pb0 = sp[kk*8+1], pb1 = sp[kk*8+3], pb2 = sp[kk*8+5], pb3 = sp[kk*8+7];
            int tl = lane >> 3;
            #pragma unroll
            for (int jj = 0; jj < 4; jj++) {
                int row = kk*16 + ((tl & 1) << 3) + (lane & 7);
                int c   = jj*2 + (tl >> 1);
                uint32_t off = (uint32_t)(row*128 + ((c ^ (row & 7)) << 4));
                uint32_t v0,v1,v2,v3, u0,u1,u2,u3;
                ldsm4t(v0, v1, v2, v3, sb + VH_ + off);
                ldsm4t(u0, u1, u2, u3, sb + VL_ + off);
                mma16816(o[2*jj  ], pa0, pa1, pa2, pa3, v0, v1);
                mma16816(o[2*jj  ], pb0, pb1, pb2, pb3, v0, v1);
                mma16816(o[2*jj  ], pa0, pa1, pa2, pa3, u0, u1);
                mma16816(o[2*jj+1], pa0, pa1, pa2, pa3, v2, v3);
                mma16816(o[2*jj+1], pb0, pb1, pb2, pb3, v2, v3);
                mma16816(o[2*jj+1], pa0, pa1, pa2, pa3, u2, u3);
            }
        }
    }

    float inv0 = 1.0f / lrow0, inv1 = 1.0f / lrow1;
    #pragma unroll
    for (int j = 0; j < 8; j++) {
        size_t oidx = (size_t)(b*TT + qrow0)*CC + h*DD + j*8 + 2*tg;
        *(uint32_t*)&yh[oidx] = packh2(o[j][0]*inv0, o[j][1]*inv0);
        oidx += (size_t)8*CC;
        *(uint32_t*)&yh[oidx] = packh2(o[j][2]*inv1, o[j][3]*inv1);
    }
}

// ---------------- launch ----------------
extern "C" void kernel_launch(void* const* d_in, const int* in_sizes, int n_in,
                              void* d_out, int out_size)
{
    (void)in_sizes; (void)n_in; (void)out_size;
    const int*   idx     = (const int*)  d_in[0];
    const float* wte     = (const float*)d_in[1];
    const float* wpe     = (const float*)d_in[2];
    const float* ln1w    = (const float*)d_in[3];
    const float* ln1b    = (const float*)d_in[4];
    const float* qkvw    = (const float*)d_in[5];
    const float* qkvb    = (const float*)d_in[6];
    const float* projw   = (const float*)d_in[7];
    const float* projb   = (const float*)d_in[8];
    const float* ln2w    = (const float*)d_in[9];
    const float* ln2b    = (const float*)d_in[10];
    const float* fcw     = (const float*)d_in[11];
    const float* fcb     = (const float*)d_in[12];
    const float* fcprojw = (const float*)d_in[13];
    const float* fcprojb = (const float*)d_in[14];
    const float* lnfw    = (const float*)d_in[15];
    const float* lnfb    = (const float*)d_in[16];
    float* out = (float*)d_out;

    float *x, *qkv;
    __half *ln, *att, *act;
    __half *qkvwh, *qkvwl, *projwh, *projwl, *fcwh, *fcwl, *fcpwh, *fcpwl, *wteh, *wtel;
    cudaGetSymbolAddress((void**)&x,    g_x);
    cudaGetSymbolAddress((void**)&qkv,  g_qkv);
    cudaGetSymbolAddress((void**)&ln,   g_ln);
    cudaGetSymbolAddress((void**)&att,  g_att);
    cudaGetSymbolAddress((void**)&act,  g_act);
    cudaGetSymbolAddress((void**)&qkvwh, g_qkvw_h); cudaGetSymbolAddress((void**)&qkvwl, g_qkvw_l);
    cudaGetSymbolAddress((void**)&projwh,g_projw_h);cudaGetSymbolAddress((void**)&projwl,g_projw_l);
    cudaGetSymbolAddress((void**)&fcwh, g_fcw_h);  cudaGetSymbolAddress((void**)&fcwl, g_fcw_l);
    cudaGetSymbolAddress((void**)&fcpwh,g_fcpw_h); cudaGetSymbolAddress((void**)&fcpwl,g_fcpw_l);
    cudaGetSymbolAddress((void**)&wteh, g_wte_h);  cudaGetSymbolAddress((void**)&wtel, g_wte_l);

    cudaFuncSetAttribute(gemm_hmma<false,false,false>, cudaFuncAttributeMaxDynamicSharedMemorySize, GSMEM);
    cudaFuncSetAttribute(gemm_hmma<false,true ,false>, cudaFuncAttributeMaxDynamicSharedMemorySize, GSMEM);
    cudaFuncSetAttribute(gemm_hmma<true ,false,true >, cudaFuncAttributeMaxDynamicSharedMemorySize, GSMEM);

    const int SB = 1184;
    split_kernel<<<SB, 256>>>(qkvw,    qkvwh,  qkvwl,  (long)LL*C3*CC/4);
    split_kernel<<<SB, 256>>>(projw,   projwh, projwl, (long)LL*CC*CC/4);
    split_kernel<<<SB, 256>>>(fcw,     fcwh,   fcwl,   (long)LL*C4*CC/4);
    split_kernel<<<SB, 256>>>(fcprojw, fcpwh,  fcpwl,  (long)LL*CC*C4/4);
    split_kernel<<<SB, 256>>>(wte,     wteh,   wtel,   (long)VP*CC/4);

    embed_kernel<<<MROWS, 256>>>(idx, wte, wpe, x);

    for (int l = 0; l < LL; l++) {
        ln_kernel<<<MROWS, 256>>>(x, ln1w + l*CC, ln1b + l*CC, ln);

        gemm_hmma<false,false,false><<<dim3(MROWS/128, C3/128), 256, GSMEM>>>(
            ln, qkvwh + (size_t)l*C3*CC, qkvwl + (size_t)l*C3*CC,
            qkvb + (size_t)l*C3, nullptr, qkv, nullptr, MROWS, C3, CC);

        attn_tc<<<dim3(TT/128, HH, BATCH), 256>>>(qkv, att);

        gemm_hmma<false,true,false><<<dim3(MROWS/128, CC/128), 256, GSMEM>>>(
            att, projwh + (size_t)l*CC*CC, projwl + (size_t)l*CC*CC,
            projb + (size_t)l*CC, x, x, nullptr, MROWS, CC, CC);

        ln_kernel<<<MROWS, 256>>>(x, ln2w + l*CC, ln2b + l*CC, ln);

        gemm_hmma<true,false,true><<<dim3(MROWS/128, C4/128), 256, GSMEM>>>(
            ln, fcwh + (size_t)l*C4*CC, fcwl + (size_t)l*C4*CC,
            fcb + (size_t)l*C4, nullptr, nullptr, act, MROWS, C4, CC);

        gemm_hmma<false,true,false><<<dim3(MROWS/128, CC/128), 256, GSMEM>>>(
            act, fcpwh + (size_t)l*CC*C4, fcpwl + (size_t)l*CC*C4,
            fcprojb + (size_t)l*CC, x, x, nullptr, MROWS, CC, C4);
    }

    ln_kernel<<<MROWS, 256>>>(x, lnfw, lnfb, ln);

    gemm_hmma<false,false,false><<<dim3(MROWS/128, VP/128), 256, GSMEM>>>(
        ln, wteh, wtel, nullptr, nullptr, out, nullptr, MROWS, VP, CC);
}